// round 14
// baseline (speedup 1.0000x reference)
#include <cuda_runtime.h>
#include <math.h>
#include <stdint.h>

#define BATCH 2
#define SEQ   1024
#define DIM   512
#define NH    8
#define HD    64
#define MROWS (BATCH*SEQ)      // 2048
#define CHK   32
#define NCHK  (SEQ/CHK)        // 32
#define NBH   (BATCH*NH)       // 16
#define NBLK  (NBH*NCHK)       // 512

// ---------------- scratch ---------------------------------------------------
__device__ float g_q  [MROWS*DIM];   // q; reused as lg_raw after chunk_out
__device__ float g_k  [MROWS*DIM];
__device__ float g_v  [MROWS*DIM];
__device__ float g_att[MROWS*DIM];
__device__ float g_o2 [MROWS*DIM];   // raw att@Wo
__device__ float g_g1 [MROWS*DIM];   // x @ Wg[:512]
__device__ float g_wf [DIM*DIM];     // Wo @ Wg2
__device__ float g_bvec[DIM];        // bo @ Wg2 + bg
__device__ float g_kv [NBLK*HD*HD];
__device__ float g_ks [NBLK*HD];

__device__ __forceinline__ float fmap(float t) {
    return t > 0.f ? t + 1.f : expf(t);
}

__device__ __forceinline__ void mma_tf32(float c[4],
    uint32_t a0, uint32_t a1, uint32_t a2, uint32_t a3,
    uint32_t b0, uint32_t b1)
{
    asm volatile(
        "mma.sync.aligned.m16n8k8.row.col.f32.tf32.tf32.f32 "
        "{%0,%1,%2,%3},{%4,%5,%6,%7},{%8,%9},{%0,%1,%2,%3};"
        : "+f"(c[0]), "+f"(c[1]), "+f"(c[2]), "+f"(c[3])
        : "r"(a0), "r"(a1), "r"(a2), "r"(a3), "r"(b0), "r"(b1));
}

__device__ __forceinline__ void cp16(void* smem_dst, const void* gsrc) {
    uint32_t d = (uint32_t)__cvta_generic_to_shared(smem_dst);
    asm volatile("cp.async.cg.shared.global [%0], [%1], 16;" :: "r"(d), "l"(gsrc));
}
#define CP_COMMIT() asm volatile("cp.async.commit_group;")
#define CP_WAIT0()  asm volatile("cp.async.wait_group 0;")

// ======================= tf32 GEMM framework ================================
// BM=128, BN=64, BK=32, 128 threads, 4 warps as 2(M)x2(N), warp tile 64x32.
#define AS_STRIDE 36
#define BS_STRIDE 72
#define AS_WORDS  (128 * AS_STRIDE)
#define BS_WORDS  (32 * BS_STRIDE)
#define GEMM_SMEM_BYTES ((2 * AS_WORDS + 2 * BS_WORDS) * 4)   // 55296

typedef uint32_t AsBuf[128][AS_STRIDE];
typedef uint32_t BsBuf[32][BS_STRIDE];

#define GEMM_SMEM \
    extern __shared__ uint32_t dynsmem[]; \
    AsBuf* As = (AsBuf*)dynsmem; \
    BsBuf* Bs = (BsBuf*)(dynsmem + 2 * AS_WORDS);

#define GEMM_IDS \
    const int tid  = threadIdx.x; \
    const int lane = tid & 31, wid = tid >> 5; \
    const int g    = lane >> 2, tg = lane & 3; \
    const int warp_m = (wid >> 1) * 64, warp_n = (wid & 1) * 32; \
    const int row0 = blockIdx.y * 128, col0 = blockIdx.x * 64;

__device__ __forceinline__ void gemm_copy_tile(
    uint32_t (*Asb)[AS_STRIDE], uint32_t (*Bsb)[BS_STRIDE], int tid,
    const float* Ag, size_t lda, const float* Bg, size_t ldb)
{
    const int ar = tid >> 3;            // 0..15
    const int ac = (tid & 7) * 4;       // 0,4,..,28
#pragma unroll
    for (int p = 0; p < 8; p++)
        cp16(&Asb[ar + p * 16][ac], Ag + (size_t)(ar + p * 16) * lda + ac);
#pragma unroll
    for (int p = 0; p < 4; p++) {
        int idx = tid + p * 128;
        int br  = idx >> 4;             // 0..31
        int bc  = (idx & 15) * 4;       // 0,4,..,60
        cp16(&Bsb[br][bc], Bg + (size_t)br * ldb + bc);
    }
    CP_COMMIT();
}

__device__ __forceinline__ void gemm_compute(
    uint32_t (*Asb)[AS_STRIDE], uint32_t (*Bsb)[BS_STRIDE],
    int warp_m, int warp_n, int g, int tg, float acc[4][4][4])
{
#pragma unroll
    for (int ks = 0; ks < 4; ks++) {
        uint32_t af[4][4];
#pragma unroll
        for (int mt = 0; mt < 4; mt++) {
            int base = warp_m + mt * 16;
            af[mt][0] = Asb[base + g    ][ks * 8 + tg];
            af[mt][1] = Asb[base + g + 8][ks * 8 + tg];
            af[mt][2] = Asb[base + g    ][ks * 8 + tg + 4];
            af[mt][3] = Asb[base + g + 8][ks * 8 + tg + 4];
        }
        uint32_t bf[4][2];
#pragma unroll
        for (int nt = 0; nt < 4; nt++) {
            int col = warp_n + nt * 8 + g;
            bf[nt][0] = Bsb[ks * 8 + tg    ][col];
            bf[nt][1] = Bsb[ks * 8 + tg + 4][col];
        }
#pragma unroll
        for (int mt = 0; mt < 4; mt++)
#pragma unroll
            for (int nt = 0; nt < 4; nt++)
                mma_tf32(acc[mt][nt], af[mt][0], af[mt][1], af[mt][2], af[mt][3],
                         bf[nt][0], bf[nt][1]);
    }
}

#define GEMM_ACC_INIT \
    float acc[4][4][4]; \
    _Pragma("unroll") \
    for (int mt = 0; mt < 4; mt++) \
        _Pragma("unroll") \
        for (int nt = 0; nt < 4; nt++) \
            _Pragma("unroll") \
            for (int i = 0; i < 4; i++) acc[mt][nt][i] = 0.f;

// ---------------- fused QKV+G1 GEMM (z: 0=q,1=k,2=v,3=g1) -------------------
__global__ __launch_bounds__(128)
void qkv_gemm_kernel(const float* __restrict__ X,
                     const float* __restrict__ Wq,
                     const float* __restrict__ Wk,
                     const float* __restrict__ Wv,
                     const float* __restrict__ Wg)
{
    GEMM_SMEM; GEMM_IDS;
    const int z = blockIdx.z;
    const float* __restrict__ Bw = (z == 0) ? Wq : (z == 1) ? Wk :
                                   (z == 2) ? Wv : Wg;
    float* __restrict__ Cc       = (z == 0) ? g_q : (z == 1) ? g_k :
                                   (z == 2) ? g_v : g_g1;

    GEMM_ACC_INIT;

    gemm_copy_tile(As[0], Bs[0], tid,
                   &X[(size_t)row0 * DIM], DIM, &Bw[col0], DIM);
    int buf = 0;
    for (int k0 = 32; k0 < DIM; k0 += 32) {
        CP_WAIT0(); __syncthreads();
        gemm_copy_tile(As[buf ^ 1], Bs[buf ^ 1], tid,
                       &X[(size_t)row0 * DIM + k0], DIM,
                       &Bw[(size_t)k0 * DIM + col0], DIM);
        gemm_compute(As[buf], Bs[buf], warp_m, warp_n, g, tg, acc);
        buf ^= 1;
    }
    CP_WAIT0(); __syncthreads();
    gemm_compute(As[buf], Bs[buf], warp_m, warp_n, g, tg, acc);

#pragma unroll
    for (int mt = 0; mt < 4; mt++) {
        int r0 = row0 + warp_m + mt * 16 + g;
#pragma unroll
        for (int nt = 0; nt < 4; nt++) {
            int c = col0 + warp_n + nt * 8 + tg * 2;
            float v0 = acc[mt][nt][0], v1 = acc[mt][nt][1];
            float v2 = acc[mt][nt][2], v3 = acc[mt][nt][3];
            if (z <= 1) { v0 = fmap(v0); v1 = fmap(v1); v2 = fmap(v2); v3 = fmap(v3); }
            *(float2*)&Cc[(size_t)r0      * DIM + c] = make_float2(v0, v1);
            *(float2*)&Cc[(size_t)(r0 + 8) * DIM + c] = make_float2(v2, v3);
        }
    }
}

// ---------------- Wf = Wo @ Wg2 (+ bvec = bo@Wg2 + bg on y==0 blocks) -------
__global__ __launch_bounds__(128)
void wfused_kernel(const float* __restrict__ Wo,
                   const float* __restrict__ Wg,
                   const float* __restrict__ bo,
                   const float* __restrict__ bg)
{
    GEMM_SMEM; GEMM_IDS;
    const float* __restrict__ Wg2 = Wg + (size_t)DIM * DIM;

    GEMM_ACC_INIT;

    gemm_copy_tile(As[0], Bs[0], tid,
                   &Wo[(size_t)row0 * DIM], DIM, &Wg2[col0], DIM);
    int buf = 0;
    for (int k0 = 32; k0 < DIM; k0 += 32) {
        CP_WAIT0(); __syncthreads();
        gemm_copy_tile(As[buf ^ 1], Bs[buf ^ 1], tid,
                       &Wo[(size_t)row0 * DIM + k0], DIM,
                       &Wg2[(size_t)k0 * DIM + col0], DIM);
        gemm_compute(As[buf], Bs[buf], warp_m, warp_n, g, tg, acc);
        buf ^= 1;
    }
    CP_WAIT0(); __syncthreads();
    gemm_compute(As[buf], Bs[buf], warp_m, warp_n, g, tg, acc);

#pragma unroll
    for (int mt = 0; mt < 4; mt++) {
        int r0 = row0 + warp_m + mt * 16 + g;
#pragma unroll
        for (int nt = 0; nt < 4; nt++) {
            int c = col0 + warp_n + nt * 8 + tg * 2;
            *(float2*)&g_wf[(size_t)r0      * DIM + c] =
                make_float2(acc[mt][nt][0], acc[mt][nt][1]);
            *(float2*)&g_wf[(size_t)(r0 + 8) * DIM + c] =
                make_float2(acc[mt][nt][2], acc[mt][nt][3]);
        }
    }

    if (blockIdx.y == 0) {
        __shared__ float red[128];
        const int cc   = col0 + (tid & 63);
        const int half = tid >> 6;               // 0 or 1
        float s = 0.f;
        const int kk0 = half * 256;
#pragma unroll 8
        for (int k = kk0; k < kk0 + 256; k++)
            s += bo[k] * Wg2[(size_t)k * DIM + cc];
        red[tid] = s;
        __syncthreads();
        if (half == 0)
            g_bvec[cc] = red[tid] + red[tid + 64] + bg[cc];
    }
}

// ---------------- epilogue GEMMs: z=0 att@Wo -> g_o2, z=1 att@Wf -> g_q -----
__global__ __launch_bounds__(128)
void og_gemm_kernel(const float* __restrict__ Wo)
{
    GEMM_SMEM; GEMM_IDS;
    const int z = blockIdx.z;
    const float* __restrict__ Bw = (z == 0) ? Wo : g_wf;
    float* __restrict__ Cc       = (z == 0) ? g_o2 : g_q;  // g_q dead: reuse as lg

    GEMM_ACC_INIT;

    gemm_copy_tile(As[0], Bs[0], tid,
                   &g_att[(size_t)row0 * DIM], DIM, &Bw[col0], DIM);
    int buf = 0;
    for (int k0 = 32; k0 < DIM; k0 += 32) {
        CP_WAIT0(); __syncthreads();
        gemm_copy_tile(As[buf ^ 1], Bs[buf ^ 1], tid,
                       &g_att[(size_t)row0 * DIM + k0], DIM,
                       &Bw[(size_t)k0 * DIM + col0], DIM);
        gemm_compute(As[buf], Bs[buf], warp_m, warp_n, g, tg, acc);
        buf ^= 1;
    }
    CP_WAIT0(); __syncthreads();
    gemm_compute(As[buf], Bs[buf], warp_m, warp_n, g, tg, acc);

#pragma unroll
    for (int mt = 0; mt < 4; mt++) {
        int r0 = row0 + warp_m + mt * 16 + g;
#pragma unroll
        for (int nt = 0; nt < 4; nt++) {
            int c = col0 + warp_n + nt * 8 + tg * 2;
            *(float2*)&Cc[(size_t)r0      * DIM + c] =
                make_float2(acc[mt][nt][0], acc[mt][nt][1]);
            *(float2*)&Cc[(size_t)(r0 + 8) * DIM + c] =
                make_float2(acc[mt][nt][2], acc[mt][nt][3]);
        }
    }
}

// ---------------- final elementwise: out = x + sig(lg)*(o2+bo - x) ----------
__global__ __launch_bounds__(256)
void final_kernel(const float* __restrict__ X,
                  const float* __restrict__ bo,
                  float* __restrict__ Out)
{
    const int i4 = (blockIdx.x * 256 + threadIdx.x) * 4;   // over MROWS*DIM
    const int c  = i4 & (DIM - 1);

    float4 xv = *(const float4*)&X[i4];
    float4 o2 = *(const float4*)&g_o2[i4];
    float4 lg = *(const float4*)&g_q [i4];
    float4 g1 = *(const float4*)&g_g1[i4];
    float4 b4 = *(const float4*)&bo[c];
    float4 bv = *(const float4*)&g_bvec[c];

    float oo[4] = {o2.x + b4.x, o2.y + b4.y, o2.z + b4.z, o2.w + b4.w};
    float ll[4] = {lg.x + bv.x + g1.x, lg.y + bv.y + g1.y,
                   lg.z + bv.z + g1.z, lg.w + bv.w + g1.w};
    float xx[4] = {xv.x, xv.y, xv.z, xv.w};
    float rr[4];
#pragma unroll
    for (int j = 0; j < 4; j++) {
        float s = 1.f / (1.f + expf(-ll[j]));
        rr[j] = xx[j] + s * (oo[j] - xx[j]);
    }
    *(float4*)&Out[i4] = make_float4(rr[0], rr[1], rr[2], rr[3]);
}

// ---------------- phase A: per-chunk kv sums (2d x 8e register tiles) -------
__global__ __launch_bounds__(256)
void chunk_sums_kernel()
{
    const int bid = blockIdx.x;
    const int c   = bid % NCHK;
    const int bh  = bid / NCHK;
    const int h   = bh % NH;
    const int b   = bh / NH;
    const int row0 = b * SEQ + c * CHK;
    const int col  = h * HD;

    __shared__ float ks[CHK][HD + 4];
    __shared__ float vs[CHK][HD + 4];
    for (int i = threadIdx.x; i < CHK * (HD / 4); i += 256) {
        int t = i / (HD / 4), d4 = (i % (HD / 4)) * 4;
        *(float4*)&ks[t][d4] =
            *(const float4*)&g_k[(size_t)(row0 + t) * DIM + col + d4];
        *(float4*)&vs[t][d4] =
            *(const float4*)&g_v[(size_t)(row0 + t) * DIM + col + d4];
    }
    __syncthreads();

    const int d0 = (threadIdx.x >> 3) * 2;
    const int e0 = (threadIdx.x & 7) * 8;
    float acc[2][8];
#pragma unroll
    for (int i = 0; i < 2; i++)
#pragma unroll
        for (int j = 0; j < 8; j++) acc[i][j] = 0.f;

#pragma unroll
    for (int t = 0; t < CHK; t++) {
        float k0 = ks[t][d0], k1 = ks[t][d0 + 1];
        float4 vA = *(const float4*)&vs[t][e0];
        float4 vB = *(const float4*)&vs[t][e0 + 4];
        acc[0][0] += k0 * vA.x; acc[0][1] += k0 * vA.y;
        acc[0][2] += k0 * vA.z; acc[0][3] += k0 * vA.w;
        acc[0][4] += k0 * vB.x; acc[0][5] += k0 * vB.y;
        acc[0][6] += k0 * vB.z; acc[0][7] += k0 * vB.w;
        acc[1][0] += k1 * vA.x; acc[1][1] += k1 * vA.y;
        acc[1][2] += k1 * vA.z; acc[1][3] += k1 * vA.w;
        acc[1][4] += k1 * vB.x; acc[1][5] += k1 * vB.y;
        acc[1][6] += k1 * vB.z; acc[1][7] += k1 * vB.w;
    }
    const int base = bid * HD * HD;
#pragma unroll
    for (int i = 0; i < 2; i++) {
        *(float4*)&g_kv[base + (d0 + i) * HD + e0] =
            make_float4(acc[i][0], acc[i][1], acc[i][2], acc[i][3]);
        *(float4*)&g_kv[base + (d0 + i) * HD + e0 + 4] =
            make_float4(acc[i][4], acc[i][5], acc[i][6], acc[i][7]);
    }

    if (threadIdx.x < HD) {
        float a = 0.f;
#pragma unroll
        for (int t = 0; t < CHK; t++) a += ks[t][threadIdx.x];
        g_ks[bid * HD + threadIdx.x] = a;
    }
}

// ---------------- phase B: exclusive prefix, depth-4 prefetch pipeline ------
__global__ __launch_bounds__(256)
void prefix_kernel()
{
    const int bh    = blockIdx.x >> 4;
    const int slice = blockIdx.x & 15;
    const int i     = slice * 256 + threadIdx.x;
    const int stride = HD * HD;
    const int base0  = bh * NCHK * stride + i;

    float buf[4];
#pragma unroll
    for (int p = 0; p < 4; p++)
        buf[p] = g_kv[base0 + p * stride];

    float run = 0.f;
#pragma unroll 4
    for (int c = 0; c < NCHK; c++) {
        float cur = buf[c & 3];
        if (c + 4 < NCHK)
            buf[c & 3] = g_kv[base0 + (c + 4) * stride];
        g_kv[base0 + c * stride] = run;
        run += cur;
    }

    if (slice == 0 && threadIdx.x < HD) {
        const int kbase = bh * NCHK * HD + threadIdx.x;
        float kb[4];
#pragma unroll
        for (int p = 0; p < 4; p++)
            kb[p] = g_ks[kbase + p * HD];
        float r = 0.f;
#pragma unroll 4
        for (int c = 0; c < NCHK; c++) {
            float cur = kb[c & 3];
            if (c + 4 < NCHK)
                kb[c & 3] = g_ks[kbase + (c + 4) * HD];
            g_ks[kbase + c * HD] = r;
            r += cur;
        }
    }
}

// ---------------- phase C: intra-chunk attention (256 thr, 2s x 4e) ---------
__global__ __launch_bounds__(256)
void chunk_out_kernel()
{
    const int bid = blockIdx.x;
    const int c   = bid % NCHK;
    const int bh  = bid / NCHK;
    const int h   = bh % NH;
    const int b   = bh / NH;
    const int row0 = b * SEQ + c * CHK;
    const int col  = h * HD;

    __shared__ float qs [CHK][HD + 4];
    __shared__ float kst_sc[HD * (CHK + 4)];
    __shared__ float vs [CHK][HD + 4];
    __shared__ float kvp[HD][HD + 4];
    __shared__ float kp [HD];
    __shared__ float den[CHK];

    float (*kst)[CHK + 4] = (float(*)[CHK + 4])kst_sc;
    float (*Sc) [CHK + 4] = (float(*)[CHK + 4])kst_sc;

    const int tid = threadIdx.x;
    for (int i = tid; i < CHK * (HD / 4); i += 256) {
        int t = i / (HD / 4), d4 = (i % (HD / 4)) * 4;
        *(float4*)&qs[t][d4] =
            *(const float4*)&g_q[(size_t)(row0 + t) * DIM + col + d4];
        float4 kv4 = *(const float4*)&g_k[(size_t)(row0 + t) * DIM + col + d4];
        kst[d4+0][t] = kv4.x; kst[d4+1][t] = kv4.y;
        kst[d4+2][t] = kv4.z; kst[d4+3][t] = kv4.w;
        *(float4*)&vs[t][d4] =
            *(const float4*)&g_v[(size_t)(row0 + t) * DIM + col + d4];
    }
    const int base = bid * HD * HD;
    for (int i = tid; i < HD * (HD / 4); i += 256) {
        int d = i / (HD / 4), e4 = (i % (HD / 4)) * 4;
        *(float4*)&kvp[d][e4] = *(const float4*)&g_kv[base + d * HD + e4];
    }
    if (tid < HD) kp[tid] = g_ks[bid * HD + tid];
    __syncthreads();

    const int s0 = (tid >> 4) * 2;

    {
        const int t0 = (tid & 15) * 2;
        float a0[2] = {0.f, 0.f};
        float a1[2] = {0.f, 0.f};
#pragma unroll
        for (int d0 = 0; d0 < HD; d0 += 4) {
            float4 qA = *(const float4*)&qs[s0][d0];
            float4 qB = *(const float4*)&qs[s0 + 1][d0];
            float2 kA = *(const float2*)&kst[d0+0][t0];
            float2 kB = *(const float2*)&kst[d0+1][t0];
            float2 kC = *(const float2*)&kst[d0+2][t0];
            float2 kD = *(const float2*)&kst[d0+3][t0];
            a0[0] += qA.x*kA.x + qA.y*kB.x + qA.z*kC.x + qA.w*kD.x;
            a0[1] += qA.x*kA.y + qA.y*kB.y + qA.z*kC.y + qA.w*kD.y;
            a1[0] += qB.x*kA.x + qB.y*kB.x + qB.z*kC.x + qB.w*kD.x;
            a1[1] += qB.x*kA.y + qB.y*kB.y + qB.z*kC.y + qB.w*kD.y;
        }
        __syncthreads();
#pragma unroll
        for (int j = 0; j < 2; j++) {
            Sc[s0    ][t0 + j] = (t0 + j <= s0    ) ? a0[j] : 0.f;
            Sc[s0 + 1][t0 + j] = (t0 + j <= s0 + 1) ? a1[j] : 0.f;
        }
    }
    __syncthreads();

    if (tid < CHK) {
        const int s = tid;
        float a = 0.f;
#pragma unroll
        for (int d0 = 0; d0 < HD; d0 += 4) {
            float4 q4 = *(const float4*)&qs[s][d0];
            float4 k4 = *(const float4*)&kp[d0];
            a += q4.x*k4.x + q4.y*k4.y + q4.z*k4.z + q4.w*k4.w;
        }
#pragma unroll
        for (int tt = 0; tt < CHK; tt += 4) {
            float4 s4 = *(const float4*)&Sc[s][tt];
            a += s4.x + s4.y + s4.z + s4.w;
        }
        den[s] = a + 1e-6f;
    }
    __syncthreads();

    {
        const int e0 = (tid & 15) * 4;
        float b0[4] = {0.f, 0.f, 0.f, 0.f};
        float b1[4] = {0.f, 0.f, 0.f, 0.f};

#pragma unroll
        for (int d0 = 0; d0 < HD; d0 += 4) {
            float4 qA = *(const float4*)&qs[s0][d0];
            float4 qB = *(const float4*)&qs[s0 + 1][d0];
            float qa[4] = {qA.x, qA.y, qA.z, qA.w};
            float qb[4] = {qB.x, qB.y, qB.z, qB.w};
#pragma unroll
            for (int dd = 0; dd < 4; dd++) {
                float4 vA = *(const float4*)&kvp[d0 + dd][e0];
                b0[0] += qa[dd] * vA.x; b0[1] += qa[dd] * vA.y;
                b0[2] += qa[dd] * vA.z; b0[3] += qa[dd] * vA.w;
                b1[0] += qb[dd] * vA.x; b1[1] += qb[dd] * vA.y;
                b1[2] += qb[dd] * vA.z; b1[3] += qb[dd] * vA.w;
            }
        }
#pragma unroll
        for (int tt0 = 0; tt0 < CHK; tt0 += 4) {
            float4 sA = *(const float4*)&Sc[s0][tt0];
            float4 sB = *(const float4*)&Sc[s0 + 1][tt0];
            float sa[4] = {sA.x, sA.y, sA.z, sA.w};
            float sb[4] = {sB.x, sB.y, sB.z, sB.w};
#pragma unroll
            for (int tt = 0; tt < 4; tt++) {
                float4 vA = *(const float4*)&vs[tt0 + tt][e0];
                b0[0] += sa[tt] * vA.x; b0[1] += sa[tt] * vA.y;
                b0[2] += sa[tt] * vA.z; b0[3] += sa[tt] * vA.w;
                b1[0] += sb[tt] * vA.x; b1[1] += sb[tt] * vA.y;
                b1[2] += sb[tt] * vA.z; b1[3] += sb[tt] * vA.w;
            }
        }
        const float inv0 = 1.f / den[s0];
        const float inv1 = 1.f / den[s0 + 1];
        float* d0p = &g_att[(size_t)(row0 + s0)     * DIM + col + e0];
        float* d1p = &g_att[(size_t)(row0 + s0 + 1) * DIM + col + e0];
        *(float4*)d0p = make_float4(b0[0]*inv0, b0[1]*inv0, b0[2]*inv0, b0[3]*inv0);
        *(float4*)d1p = make_float4(b1[0]*inv1, b1[1]*inv1, b1[2]*inv1, b1[3]*inv1);
    }
}

// ---------------- launcher --------------------------------------------------
extern "C" void kernel_launch(void* const* d_in, const int* in_sizes, int n_in,
                              void* d_out, int out_size)
{
    const float* x  = (const float*)d_in[0];
    const float* Wq = (const float*)d_in[1];
    const float* Wk = (const float*)d_in[2];
    const float* Wv = (const float*)d_in[3];
    const float* Wo = (const float*)d_in[4];
    const float* bo = (const float*)d_in[5];
    const float* Wg = (const float*)d_in[6];
    const float* bg = (const float*)d_in[7];
    float* out = (float*)d_out;

    cudaFuncSetAttribute(qkv_gemm_kernel,
        cudaFuncAttributeMaxDynamicSharedMemorySize, GEMM_SMEM_BYTES);
    cudaFuncSetAttribute(wfused_kernel,
        cudaFuncAttributeMaxDynamicSharedMemorySize, GEMM_SMEM_BYTES);
    cudaFuncSetAttribute(og_gemm_kernel,
        cudaFuncAttributeMaxDynamicSharedMemorySize, GEMM_SMEM_BYTES);

    dim3 gridW(DIM / 64, DIM / 128, 1);     // (8, 4)   Wf
    dim3 grid4(DIM / 64, MROWS / 128, 4);   // fused QKV + G1
    dim3 grid2(DIM / 64, MROWS / 128, 2);   // o2 + lg in one wave

    wfused_kernel<<<gridW, 128, GEMM_SMEM_BYTES>>>(Wo, Wg, bo, bg);
    qkv_gemm_kernel<<<grid4, 128, GEMM_SMEM_BYTES>>>(x, Wq, Wk, Wv, Wg);
    chunk_sums_kernel<<<NBLK, 256>>>();
    prefix_kernel<<<NBH * 16, 256>>>();
    chunk_out_kernel<<<NBLK, 256>>>();
    og_gemm_kernel<<<grid2, 128, GEMM_SMEM_BYTES>>>(Wo);
    final_kernel<<<MROWS * DIM / 1024, 256>>>(x, bo, out);
}

// round 15
// speedup vs baseline: 1.0357x; 1.0357x over previous
#include <cuda_runtime.h>
#include <math.h>
#include <stdint.h>

#define BATCH 2
#define SEQ   1024
#define DIM   512
#define NH    8
#define HD    64
#define MROWS (BATCH*SEQ)      // 2048
#define CHK   32
#define NCHK  (SEQ/CHK)        // 32
#define NBH   (BATCH*NH)       // 16
#define NBLK  (NBH*NCHK)       // 512

// ---------------- scratch ---------------------------------------------------
__device__ float g_q  [MROWS*DIM];   // q; reused as lg_raw after chunk_out
__device__ float g_k  [MROWS*DIM];
__device__ float g_v  [MROWS*DIM];
__device__ float g_att[MROWS*DIM];
__device__ float g_o2 [MROWS*DIM];   // raw att@Wo
__device__ float g_g1 [MROWS*DIM];   // x @ Wg[:512]
__device__ float g_wf [DIM*DIM];     // Wo @ Wg2
__device__ float g_bvec[DIM];        // bo @ Wg2 + bg
__device__ float g_kv [NBLK*HD*HD];
__device__ float g_ks [NBLK*HD];

__device__ __forceinline__ float fmap(float t) {
    return t > 0.f ? t + 1.f : expf(t);
}

__device__ __forceinline__ void mma_tf32(float c[4],
    uint32_t a0, uint32_t a1, uint32_t a2, uint32_t a3,
    uint32_t b0, uint32_t b1)
{
    asm volatile(
        "mma.sync.aligned.m16n8k8.row.col.f32.tf32.tf32.f32 "
        "{%0,%1,%2,%3},{%4,%5,%6,%7},{%8,%9},{%0,%1,%2,%3};"
        : "+f"(c[0]), "+f"(c[1]), "+f"(c[2]), "+f"(c[3])
        : "r"(a0), "r"(a1), "r"(a2), "r"(a3), "r"(b0), "r"(b1));
}

__device__ __forceinline__ void cp16(void* smem_dst, const void* gsrc) {
    uint32_t d = (uint32_t)__cvta_generic_to_shared(smem_dst);
    asm volatile("cp.async.cg.shared.global [%0], [%1], 16;" :: "r"(d), "l"(gsrc));
}
#define CP_COMMIT() asm volatile("cp.async.commit_group;")
#define CP_WAIT0()  asm volatile("cp.async.wait_group 0;")

// ======================= tf32 GEMM framework ================================
// BM=128, BN=64, BK=32, 128 threads, 4 warps as 2(M)x2(N), warp tile 64x32.
#define AS_STRIDE 36
#define BS_STRIDE 72
#define AS_WORDS  (128 * AS_STRIDE)
#define BS_WORDS  (32 * BS_STRIDE)
#define GEMM_SMEM_BYTES ((2 * AS_WORDS + 2 * BS_WORDS) * 4)   // 55296

typedef uint32_t AsBuf[128][AS_STRIDE];
typedef uint32_t BsBuf[32][BS_STRIDE];

#define GEMM_SMEM \
    extern __shared__ uint32_t dynsmem[]; \
    AsBuf* As = (AsBuf*)dynsmem; \
    BsBuf* Bs = (BsBuf*)(dynsmem + 2 * AS_WORDS);

#define GEMM_IDS \
    const int tid  = threadIdx.x; \
    const int lane = tid & 31, wid = tid >> 5; \
    const int g    = lane >> 2, tg = lane & 3; \
    const int warp_m = (wid >> 1) * 64, warp_n = (wid & 1) * 32; \
    const int row0 = blockIdx.y * 128, col0 = blockIdx.x * 64;

__device__ __forceinline__ void gemm_copy_tile(
    uint32_t (*Asb)[AS_STRIDE], uint32_t (*Bsb)[BS_STRIDE], int tid,
    const float* Ag, size_t lda, const float* Bg, size_t ldb)
{
    const int ar = tid >> 3;            // 0..15
    const int ac = (tid & 7) * 4;       // 0,4,..,28
#pragma unroll
    for (int p = 0; p < 8; p++)
        cp16(&Asb[ar + p * 16][ac], Ag + (size_t)(ar + p * 16) * lda + ac);
#pragma unroll
    for (int p = 0; p < 4; p++) {
        int idx = tid + p * 128;
        int br  = idx >> 4;             // 0..31
        int bc  = (idx & 15) * 4;       // 0,4,..,60
        cp16(&Bsb[br][bc], Bg + (size_t)br * ldb + bc);
    }
    CP_COMMIT();
}

__device__ __forceinline__ void gemm_compute(
    uint32_t (*Asb)[AS_STRIDE], uint32_t (*Bsb)[BS_STRIDE],
    int warp_m, int warp_n, int g, int tg, float acc[4][4][4])
{
#pragma unroll
    for (int ks = 0; ks < 4; ks++) {
        uint32_t af[4][4];
#pragma unroll
        for (int mt = 0; mt < 4; mt++) {
            int base = warp_m + mt * 16;
            af[mt][0] = Asb[base + g    ][ks * 8 + tg];
            af[mt][1] = Asb[base + g + 8][ks * 8 + tg];
            af[mt][2] = Asb[base + g    ][ks * 8 + tg + 4];
            af[mt][3] = Asb[base + g + 8][ks * 8 + tg + 4];
        }
        uint32_t bf[4][2];
#pragma unroll
        for (int nt = 0; nt < 4; nt++) {
            int col = warp_n + nt * 8 + g;
            bf[nt][0] = Bsb[ks * 8 + tg    ][col];
            bf[nt][1] = Bsb[ks * 8 + tg + 4][col];
        }
#pragma unroll
        for (int mt = 0; mt < 4; mt++)
#pragma unroll
            for (int nt = 0; nt < 4; nt++)
                mma_tf32(acc[mt][nt], af[mt][0], af[mt][1], af[mt][2], af[mt][3],
                         bf[nt][0], bf[nt][1]);
    }
}

#define GEMM_ACC_INIT \
    float acc[4][4][4]; \
    _Pragma("unroll") \
    for (int mt = 0; mt < 4; mt++) \
        _Pragma("unroll") \
        for (int nt = 0; nt < 4; nt++) \
            _Pragma("unroll") \
            for (int i = 0; i < 4; i++) acc[mt][nt][i] = 0.f;

// ---------------- fused QKV+G1 GEMM (z: 0=q,1=k,2=v,3=g1) -------------------
__global__ __launch_bounds__(128)
void qkv_gemm_kernel(const float* __restrict__ X,
                     const float* __restrict__ Wq,
                     const float* __restrict__ Wk,
                     const float* __restrict__ Wv,
                     const float* __restrict__ Wg)
{
    GEMM_SMEM; GEMM_IDS;
    const int z = blockIdx.z;
    const float* __restrict__ Bw = (z == 0) ? Wq : (z == 1) ? Wk :
                                   (z == 2) ? Wv : Wg;
    float* __restrict__ Cc       = (z == 0) ? g_q : (z == 1) ? g_k :
                                   (z == 2) ? g_v : g_g1;

    GEMM_ACC_INIT;

    gemm_copy_tile(As[0], Bs[0], tid,
                   &X[(size_t)row0 * DIM], DIM, &Bw[col0], DIM);
    int buf = 0;
    for (int k0 = 32; k0 < DIM; k0 += 32) {
        CP_WAIT0(); __syncthreads();
        gemm_copy_tile(As[buf ^ 1], Bs[buf ^ 1], tid,
                       &X[(size_t)row0 * DIM + k0], DIM,
                       &Bw[(size_t)k0 * DIM + col0], DIM);
        gemm_compute(As[buf], Bs[buf], warp_m, warp_n, g, tg, acc);
        buf ^= 1;
    }
    CP_WAIT0(); __syncthreads();
    gemm_compute(As[buf], Bs[buf], warp_m, warp_n, g, tg, acc);

#pragma unroll
    for (int mt = 0; mt < 4; mt++) {
        int r0 = row0 + warp_m + mt * 16 + g;
#pragma unroll
        for (int nt = 0; nt < 4; nt++) {
            int c = col0 + warp_n + nt * 8 + tg * 2;
            float v0 = acc[mt][nt][0], v1 = acc[mt][nt][1];
            float v2 = acc[mt][nt][2], v3 = acc[mt][nt][3];
            if (z <= 1) { v0 = fmap(v0); v1 = fmap(v1); v2 = fmap(v2); v3 = fmap(v3); }
            *(float2*)&Cc[(size_t)r0      * DIM + c] = make_float2(v0, v1);
            *(float2*)&Cc[(size_t)(r0 + 8) * DIM + c] = make_float2(v2, v3);
        }
    }
}

// ---------------- Wf = Wo @ Wg2 (+ bvec = bo@Wg2 + bg on y==0 blocks) -------
__global__ __launch_bounds__(128)
void wfused_kernel(const float* __restrict__ Wo,
                   const float* __restrict__ Wg,
                   const float* __restrict__ bo,
                   const float* __restrict__ bg)
{
    GEMM_SMEM; GEMM_IDS;
    const float* __restrict__ Wg2 = Wg + (size_t)DIM * DIM;

    GEMM_ACC_INIT;

    gemm_copy_tile(As[0], Bs[0], tid,
                   &Wo[(size_t)row0 * DIM], DIM, &Wg2[col0], DIM);
    int buf = 0;
    for (int k0 = 32; k0 < DIM; k0 += 32) {
        CP_WAIT0(); __syncthreads();
        gemm_copy_tile(As[buf ^ 1], Bs[buf ^ 1], tid,
                       &Wo[(size_t)row0 * DIM + k0], DIM,
                       &Wg2[(size_t)k0 * DIM + col0], DIM);
        gemm_compute(As[buf], Bs[buf], warp_m, warp_n, g, tg, acc);
        buf ^= 1;
    }
    CP_WAIT0(); __syncthreads();
    gemm_compute(As[buf], Bs[buf], warp_m, warp_n, g, tg, acc);

#pragma unroll
    for (int mt = 0; mt < 4; mt++) {
        int r0 = row0 + warp_m + mt * 16 + g;
#pragma unroll
        for (int nt = 0; nt < 4; nt++) {
            int c = col0 + warp_n + nt * 8 + tg * 2;
            *(float2*)&g_wf[(size_t)r0      * DIM + c] =
                make_float2(acc[mt][nt][0], acc[mt][nt][1]);
            *(float2*)&g_wf[(size_t)(r0 + 8) * DIM + c] =
                make_float2(acc[mt][nt][2], acc[mt][nt][3]);
        }
    }

    if (blockIdx.y == 0) {
        __shared__ float red[128];
        const int cc   = col0 + (tid & 63);
        const int half = tid >> 6;               // 0 or 1
        float s = 0.f;
        const int kk0 = half * 256;
#pragma unroll 8
        for (int k = kk0; k < kk0 + 256; k++)
            s += bo[k] * Wg2[(size_t)k * DIM + cc];
        red[tid] = s;
        __syncthreads();
        if (half == 0)
            g_bvec[cc] = red[tid] + red[tid + 64] + bg[cc];
    }
}

// ---------------- epilogue GEMMs: z=0 att@Wo -> g_o2, z=1 att@Wf -> g_q -----
__global__ __launch_bounds__(128)
void og_gemm_kernel(const float* __restrict__ Wo)
{
    GEMM_SMEM; GEMM_IDS;
    const int z = blockIdx.z;
    const float* __restrict__ Bw = (z == 0) ? Wo : g_wf;
    float* __restrict__ Cc       = (z == 0) ? g_o2 : g_q;  // g_q dead: reuse as lg

    GEMM_ACC_INIT;

    gemm_copy_tile(As[0], Bs[0], tid,
                   &g_att[(size_t)row0 * DIM], DIM, &Bw[col0], DIM);
    int buf = 0;
    for (int k0 = 32; k0 < DIM; k0 += 32) {
        CP_WAIT0(); __syncthreads();
        gemm_copy_tile(As[buf ^ 1], Bs[buf ^ 1], tid,
                       &g_att[(size_t)row0 * DIM + k0], DIM,
                       &Bw[(size_t)k0 * DIM + col0], DIM);
        gemm_compute(As[buf], Bs[buf], warp_m, warp_n, g, tg, acc);
        buf ^= 1;
    }
    CP_WAIT0(); __syncthreads();
    gemm_compute(As[buf], Bs[buf], warp_m, warp_n, g, tg, acc);

#pragma unroll
    for (int mt = 0; mt < 4; mt++) {
        int r0 = row0 + warp_m + mt * 16 + g;
#pragma unroll
        for (int nt = 0; nt < 4; nt++) {
            int c = col0 + warp_n + nt * 8 + tg * 2;
            *(float2*)&Cc[(size_t)r0      * DIM + c] =
                make_float2(acc[mt][nt][0], acc[mt][nt][1]);
            *(float2*)&Cc[(size_t)(r0 + 8) * DIM + c] =
                make_float2(acc[mt][nt][2], acc[mt][nt][3]);
        }
    }
}

// ---------------- final elementwise: out = x + sig(lg)*(o2+bo - x) ----------
__global__ __launch_bounds__(256)
void final_kernel(const float* __restrict__ X,
                  const float* __restrict__ bo,
                  float* __restrict__ Out)
{
    const int i4 = (blockIdx.x * 256 + threadIdx.x) * 4;   // over MROWS*DIM
    const int c  = i4 & (DIM - 1);

    float4 xv = *(const float4*)&X[i4];
    float4 o2 = *(const float4*)&g_o2[i4];
    float4 lg = *(const float4*)&g_q [i4];
    float4 g1 = *(const float4*)&g_g1[i4];
    float4 b4 = *(const float4*)&bo[c];
    float4 bv = *(const float4*)&g_bvec[c];

    float oo[4] = {o2.x + b4.x, o2.y + b4.y, o2.z + b4.z, o2.w + b4.w};
    float ll[4] = {lg.x + bv.x + g1.x, lg.y + bv.y + g1.y,
                   lg.z + bv.z + g1.z, lg.w + bv.w + g1.w};
    float xx[4] = {xv.x, xv.y, xv.z, xv.w};
    float rr[4];
#pragma unroll
    for (int j = 0; j < 4; j++) {
        float s = 1.f / (1.f + expf(-ll[j]));
        rr[j] = xx[j] + s * (oo[j] - xx[j]);
    }
    *(float4*)&Out[i4] = make_float4(rr[0], rr[1], rr[2], rr[3]);
}

// ---------------- phase A: per-chunk kv sums (2d x 8e register tiles) -------
__global__ __launch_bounds__(256)
void chunk_sums_kernel()
{
    const int bid = blockIdx.x;
    const int c   = bid % NCHK;
    const int bh  = bid / NCHK;
    const int h   = bh % NH;
    const int b   = bh / NH;
    const int row0 = b * SEQ + c * CHK;
    const int col  = h * HD;

    __shared__ float ks[CHK][HD + 4];
    __shared__ float vs[CHK][HD + 4];
    for (int i = threadIdx.x; i < CHK * (HD / 4); i += 256) {
        int t = i / (HD / 4), d4 = (i % (HD / 4)) * 4;
        *(float4*)&ks[t][d4] =
            *(const float4*)&g_k[(size_t)(row0 + t) * DIM + col + d4];
        *(float4*)&vs[t][d4] =
            *(const float4*)&g_v[(size_t)(row0 + t) * DIM + col + d4];
    }
    __syncthreads();

    const int d0 = (threadIdx.x >> 3) * 2;
    const int e0 = (threadIdx.x & 7) * 8;
    float acc[2][8];
#pragma unroll
    for (int i = 0; i < 2; i++)
#pragma unroll
        for (int j = 0; j < 8; j++) acc[i][j] = 0.f;

#pragma unroll
    for (int t = 0; t < CHK; t++) {
        float k0 = ks[t][d0], k1 = ks[t][d0 + 1];
        float4 vA = *(const float4*)&vs[t][e0];
        float4 vB = *(const float4*)&vs[t][e0 + 4];
        acc[0][0] += k0 * vA.x; acc[0][1] += k0 * vA.y;
        acc[0][2] += k0 * vA.z; acc[0][3] += k0 * vA.w;
        acc[0][4] += k0 * vB.x; acc[0][5] += k0 * vB.y;
        acc[0][6] += k0 * vB.z; acc[0][7] += k0 * vB.w;
        acc[1][0] += k1 * vA.x; acc[1][1] += k1 * vA.y;
        acc[1][2] += k1 * vA.z; acc[1][3] += k1 * vA.w;
        acc[1][4] += k1 * vB.x; acc[1][5] += k1 * vB.y;
        acc[1][6] += k1 * vB.z; acc[1][7] += k1 * vB.w;
    }
    const int base = bid * HD * HD;
#pragma unroll
    for (int i = 0; i < 2; i++) {
        *(float4*)&g_kv[base + (d0 + i) * HD + e0] =
            make_float4(acc[i][0], acc[i][1], acc[i][2], acc[i][3]);
        *(float4*)&g_kv[base + (d0 + i) * HD + e0 + 4] =
            make_float4(acc[i][4], acc[i][5], acc[i][6], acc[i][7]);
    }

    if (threadIdx.x < HD) {
        float a = 0.f;
#pragma unroll
        for (int t = 0; t < CHK; t++) a += ks[t][threadIdx.x];
        g_ks[bid * HD + threadIdx.x] = a;
    }
}

// ---------------- phase B: exclusive prefix, one element per thread ---------
__global__ __launch_bounds__(256)
void prefix_kernel()
{
    const int bh    = blockIdx.x >> 4;            // 0..15
    const int slice = blockIdx.x & 15;            // 0..15
    const int i     = slice * 256 + threadIdx.x;  // 0..4095
    float run = 0.f;
    for (int c = 0; c < NCHK; c++) {
        int idx = (bh * NCHK + c) * HD * HD + i;
        float t = g_kv[idx];
        g_kv[idx] = run;
        run += t;
    }
    if (slice == 0 && threadIdx.x < HD) {
        float r = 0.f;
        for (int c = 0; c < NCHK; c++) {
            int idx = (bh * NCHK + c) * HD + threadIdx.x;
            float t = g_ks[idx];
            g_ks[idx] = r;
            r += t;
        }
    }
}

// ---------------- phase C: intra-chunk attention (256 thr, 2s x 4e) ---------
__global__ __launch_bounds__(256)
void chunk_out_kernel()
{
    const int bid = blockIdx.x;
    const int c   = bid % NCHK;
    const int bh  = bid / NCHK;
    const int h   = bh % NH;
    const int b   = bh / NH;
    const int row0 = b * SEQ + c * CHK;
    const int col  = h * HD;

    __shared__ float qs [CHK][HD + 4];
    __shared__ float kst_sc[HD * (CHK + 4)];
    __shared__ float vs [CHK][HD + 4];
    __shared__ float kvp[HD][HD + 4];
    __shared__ float kp [HD];
    __shared__ float den[CHK];

    float (*kst)[CHK + 4] = (float(*)[CHK + 4])kst_sc;
    float (*Sc) [CHK + 4] = (float(*)[CHK + 4])kst_sc;

    const int tid = threadIdx.x;
    for (int i = tid; i < CHK * (HD / 4); i += 256) {
        int t = i / (HD / 4), d4 = (i % (HD / 4)) * 4;
        *(float4*)&qs[t][d4] =
            *(const float4*)&g_q[(size_t)(row0 + t) * DIM + col + d4];
        float4 kv4 = *(const float4*)&g_k[(size_t)(row0 + t) * DIM + col + d4];
        kst[d4+0][t] = kv4.x; kst[d4+1][t] = kv4.y;
        kst[d4+2][t] = kv4.z; kst[d4+3][t] = kv4.w;
        *(float4*)&vs[t][d4] =
            *(const float4*)&g_v[(size_t)(row0 + t) * DIM + col + d4];
    }
    const int base = bid * HD * HD;
    for (int i = tid; i < HD * (HD / 4); i += 256) {
        int d = i / (HD / 4), e4 = (i % (HD / 4)) * 4;
        *(float4*)&kvp[d][e4] = *(const float4*)&g_kv[base + d * HD + e4];
    }
    if (tid < HD) kp[tid] = g_ks[bid * HD + tid];
    __syncthreads();

    const int s0 = (tid >> 4) * 2;

    {
        const int t0 = (tid & 15) * 2;
        float a0[2] = {0.f, 0.f};
        float a1[2] = {0.f, 0.f};
#pragma unroll
        for (int d0 = 0; d0 < HD; d0 += 4) {
            float4 qA = *(const float4*)&qs[s0][d0];
            float4 qB = *(const float4*)&qs[s0 + 1][d0];
            float2 kA = *(const float2*)&kst[d0+0][t0];
            float2 kB = *(const float2*)&kst[d0+1][t0];
            float2 kC = *(const float2*)&kst[d0+2][t0];
            float2 kD = *(const float2*)&kst[d0+3][t0];
            a0[0] += qA.x*kA.x + qA.y*kB.x + qA.z*kC.x + qA.w*kD.x;
            a0[1] += qA.x*kA.y + qA.y*kB.y + qA.z*kC.y + qA.w*kD.y;
            a1[0] += qB.x*kA.x + qB.y*kB.x + qB.z*kC.x + qB.w*kD.x;
            a1[1] += qB.x*kA.y + qB.y*kB.y + qB.z*kC.y + qB.w*kD.y;
        }
        __syncthreads();
#pragma unroll
        for (int j = 0; j < 2; j++) {
            Sc[s0    ][t0 + j] = (t0 + j <= s0    ) ? a0[j] : 0.f;
            Sc[s0 + 1][t0 + j] = (t0 + j <= s0 + 1) ? a1[j] : 0.f;
        }
    }
    __syncthreads();

    if (tid < CHK) {
        const int s = tid;
        float a = 0.f;
#pragma unroll
        for (int d0 = 0; d0 < HD; d0 += 4) {
            float4 q4 = *(const float4*)&qs[s][d0];
            float4 k4 = *(const float4*)&kp[d0];
            a += q4.x*k4.x + q4.y*k4.y + q4.z*k4.z + q4.w*k4.w;
        }
#pragma unroll
        for (int tt = 0; tt < CHK; tt += 4) {
            float4 s4 = *(const float4*)&Sc[s][tt];
            a += s4.x + s4.y + s4.z + s4.w;
        }
        den[s] = a + 1e-6f;
    }
    __syncthreads();

    {
        const int e0 = (tid & 15) * 4;
        float b0[4] = {0.f, 0.f, 0.f, 0.f};
        float b1[4] = {0.f, 0.f, 0.f, 0.f};

#pragma unroll
        for (int d0 = 0; d0 < HD; d0 += 4) {
            float4 qA = *(const float4*)&qs[s0][d0];
            float4 qB = *(const float4*)&qs[s0 + 1][d0];
            float qa[4] = {qA.x, qA.y, qA.z, qA.w};
            float qb[4] = {qB.x, qB.y, qB.z, qB.w};
#pragma unroll
            for (int dd = 0; dd < 4; dd++) {
                float4 vA = *(const float4*)&kvp[d0 + dd][e0];
                b0[0] += qa[dd] * vA.x; b0[1] += qa[dd] * vA.y;
                b0[2] += qa[dd] * vA.z; b0[3] += qa[dd] * vA.w;
                b1[0] += qb[dd] * vA.x; b1[1] += qb[dd] * vA.y;
                b1[2] += qb[dd] * vA.z; b1[3] += qb[dd] * vA.w;
            }
        }
#pragma unroll
        for (int tt0 = 0; tt0 < CHK; tt0 += 4) {
            float4 sA = *(const float4*)&Sc[s0][tt0];
            float4 sB = *(const float4*)&Sc[s0 + 1][tt0];
            float sa[4] = {sA.x, sA.y, sA.z, sA.w};
            float sb[4] = {sB.x, sB.y, sB.z, sB.w};
#pragma unroll
            for (int tt = 0; tt < 4; tt++) {
                float4 vA = *(const float4*)&vs[tt0 + tt][e0];
                b0[0] += sa[tt] * vA.x; b0[1] += sa[tt] * vA.y;
                b0[2] += sa[tt] * vA.z; b0[3] += sa[tt] * vA.w;
                b1[0] += sb[tt] * vA.x; b1[1] += sb[tt] * vA.y;
                b1[2] += sb[tt] * vA.z; b1[3] += sb[tt] * vA.w;
            }
        }
        const float inv0 = 1.f / den[s0];
        const float inv1 = 1.f / den[s0 + 1];
        float* d0p = &g_att[(size_t)(row0 + s0)     * DIM + col + e0];
        float* d1p = &g_att[(size_t)(row0 + s0 + 1) * DIM + col + e0];
        *(float4*)d0p = make_float4(b0[0]*inv0, b0[1]*inv0, b0[2]*inv0, b0[3]*inv0);
        *(float4*)d1p = make_float4(b1[0]*inv1, b1[1]*inv1, b1[2]*inv1, b1[3]*inv1);
    }
}

// ---------------- launcher --------------------------------------------------
extern "C" void kernel_launch(void* const* d_in, const int* in_sizes, int n_in,
                              void* d_out, int out_size)
{
    const float* x  = (const float*)d_in[0];
    const float* Wq = (const float*)d_in[1];
    const float* Wk = (const float*)d_in[2];
    const float* Wv = (const float*)d_in[3];
    const float* Wo = (const float*)d_in[4];
    const float* bo = (const float*)d_in[5];
    const float* Wg = (const float*)d_in[6];
    const float* bg = (const float*)d_in[7];
    float* out = (float*)d_out;

    cudaFuncSetAttribute(qkv_gemm_kernel,
        cudaFuncAttributeMaxDynamicSharedMemorySize, GEMM_SMEM_BYTES);
    cudaFuncSetAttribute(wfused_kernel,
        cudaFuncAttributeMaxDynamicSharedMemorySize, GEMM_SMEM_BYTES);
    cudaFuncSetAttribute(og_gemm_kernel,
        cudaFuncAttributeMaxDynamicSharedMemorySize, GEMM_SMEM_BYTES);

    dim3 gridW(DIM / 64, DIM / 128, 1);     // (8, 4)   Wf
    dim3 grid4(DIM / 64, MROWS / 128, 4);   // fused QKV + G1
    dim3 grid2(DIM / 64, MROWS / 128, 2);   // o2 + lg in one wave

    wfused_kernel<<<gridW, 128, GEMM_SMEM_BYTES>>>(Wo, Wg, bo, bg);
    qkv_gemm_kernel<<<grid4, 128, GEMM_SMEM_BYTES>>>(x, Wq, Wk, Wv, Wg);
    chunk_sums_kernel<<<NBLK, 256>>>();
    prefix_kernel<<<NBH * 16, 256>>>();
    chunk_out_kernel<<<NBLK, 256>>>();
    og_gemm_kernel<<<grid2, 128, GEMM_SMEM_BYTES>>>(Wo);
    final_kernel<<<MROWS * DIM / 1024, 256>>>(x, bo, out);
}

// round 16
// speedup vs baseline: 1.1604x; 1.1204x over previous
#include <cuda_runtime.h>
#include <math.h>
#include <stdint.h>

#define BATCH 2
#define SEQ   1024
#define DIM   512
#define NH    8
#define HD    64
#define MROWS (BATCH*SEQ)      // 2048
#define CHK   32
#define NCHK  (SEQ/CHK)        // 32
#define NBH   (BATCH*NH)       // 16
#define NBLK  (NBH*NCHK)       // 512

// ---------------- scratch ---------------------------------------------------
__device__ float g_q  [MROWS*DIM];   // q; reused as lg_raw after chunk_out
__device__ float g_k  [MROWS*DIM];
__device__ float g_v  [MROWS*DIM];
__device__ float g_att[MROWS*DIM];
__device__ float g_o2 [MROWS*DIM];   // raw att@Wo
__device__ float g_g1 [MROWS*DIM];   // x @ Wg[:512]
__device__ float g_wf [DIM*DIM];     // Wo @ Wg2
__device__ float g_bvec[DIM];        // bo @ Wg2 + bg
__device__ float g_kv [NBLK*HD*HD];
__device__ float g_ks [NBLK*HD];

__device__ __forceinline__ float fmap(float t) {
    return t > 0.f ? t + 1.f : expf(t);
}

__device__ __forceinline__ void mma_tf32(float c[4],
    uint32_t a0, uint32_t a1, uint32_t a2, uint32_t a3,
    uint32_t b0, uint32_t b1)
{
    asm volatile(
        "mma.sync.aligned.m16n8k8.row.col.f32.tf32.tf32.f32 "
        "{%0,%1,%2,%3},{%4,%5,%6,%7},{%8,%9},{%0,%1,%2,%3};"
        : "+f"(c[0]), "+f"(c[1]), "+f"(c[2]), "+f"(c[3])
        : "r"(a0), "r"(a1), "r"(a2), "r"(a3), "r"(b0), "r"(b1));
}

__device__ __forceinline__ void cp16(void* smem_dst, const void* gsrc) {
    uint32_t d = (uint32_t)__cvta_generic_to_shared(smem_dst);
    asm volatile("cp.async.cg.shared.global [%0], [%1], 16;" :: "r"(d), "l"(gsrc));
}
#define CP_COMMIT() asm volatile("cp.async.commit_group;")
#define CP_WAIT0()  asm volatile("cp.async.wait_group 0;")

// ======================= tf32 GEMM framework ================================
// BM=128, BN=64, BK=32, 128 threads, 4 warps as 2(M)x2(N), warp tile 64x32.
#define AS_STRIDE 36
#define BS_STRIDE 72
#define AS_WORDS  (128 * AS_STRIDE)
#define BS_WORDS  (32 * BS_STRIDE)
#define GEMM_SMEM_BYTES ((2 * AS_WORDS + 2 * BS_WORDS) * 4)   // 55296

typedef uint32_t AsBuf[128][AS_STRIDE];
typedef uint32_t BsBuf[32][BS_STRIDE];

#define GEMM_SMEM \
    extern __shared__ uint32_t dynsmem[]; \
    AsBuf* As = (AsBuf*)dynsmem; \
    BsBuf* Bs = (BsBuf*)(dynsmem + 2 * AS_WORDS);

#define GEMM_IDS \
    const int tid  = threadIdx.x; \
    const int lane = tid & 31, wid = tid >> 5; \
    const int g    = lane >> 2, tg = lane & 3; \
    const int warp_m = (wid >> 1) * 64, warp_n = (wid & 1) * 32; \
    const int row0 = blockIdx.y * 128, col0 = blockIdx.x * 64;

__device__ __forceinline__ void gemm_copy_tile(
    uint32_t (*Asb)[AS_STRIDE], uint32_t (*Bsb)[BS_STRIDE], int tid,
    const float* Ag, size_t lda, const float* Bg, size_t ldb)
{
    const int ar = tid >> 3;            // 0..15
    const int ac = (tid & 7) * 4;       // 0,4,..,28
#pragma unroll
    for (int p = 0; p < 8; p++)
        cp16(&Asb[ar + p * 16][ac], Ag + (size_t)(ar + p * 16) * lda + ac);
#pragma unroll
    for (int p = 0; p < 4; p++) {
        int idx = tid + p * 128;
        int br  = idx >> 4;             // 0..31
        int bc  = (idx & 15) * 4;       // 0,4,..,60
        cp16(&Bsb[br][bc], Bg + (size_t)br * ldb + bc);
    }
    CP_COMMIT();
}

__device__ __forceinline__ void gemm_compute(
    uint32_t (*Asb)[AS_STRIDE], uint32_t (*Bsb)[BS_STRIDE],
    int warp_m, int warp_n, int g, int tg, float acc[4][4][4])
{
#pragma unroll
    for (int ks = 0; ks < 4; ks++) {
        uint32_t af[4][4];
#pragma unroll
        for (int mt = 0; mt < 4; mt++) {
            int base = warp_m + mt * 16;
            af[mt][0] = Asb[base + g    ][ks * 8 + tg];
            af[mt][1] = Asb[base + g + 8][ks * 8 + tg];
            af[mt][2] = Asb[base + g    ][ks * 8 + tg + 4];
            af[mt][3] = Asb[base + g + 8][ks * 8 + tg + 4];
        }
        uint32_t bf[4][2];
#pragma unroll
        for (int nt = 0; nt < 4; nt++) {
            int col = warp_n + nt * 8 + g;
            bf[nt][0] = Bsb[ks * 8 + tg    ][col];
            bf[nt][1] = Bsb[ks * 8 + tg + 4][col];
        }
#pragma unroll
        for (int mt = 0; mt < 4; mt++)
#pragma unroll
            for (int nt = 0; nt < 4; nt++)
                mma_tf32(acc[mt][nt], af[mt][0], af[mt][1], af[mt][2], af[mt][3],
                         bf[nt][0], bf[nt][1]);
    }
}

#define GEMM_ACC_INIT \
    float acc[4][4][4]; \
    _Pragma("unroll") \
    for (int mt = 0; mt < 4; mt++) \
        _Pragma("unroll") \
        for (int nt = 0; nt < 4; nt++) \
            _Pragma("unroll") \
            for (int i = 0; i < 4; i++) acc[mt][nt][i] = 0.f;

// ------- fused QKV+G1+Wf GEMM (z: 0=q,1=k,2=v,3=g1,4=Wf[y<4]) ---------------
__global__ __launch_bounds__(128)
void qkv_gemm_kernel(const float* __restrict__ X,
                     const float* __restrict__ Wq,
                     const float* __restrict__ Wk,
                     const float* __restrict__ Wv,
                     const float* __restrict__ Wo,
                     const float* __restrict__ Wg,
                     const float* __restrict__ bo,
                     const float* __restrict__ bg)
{
    const int z = blockIdx.z;
    if (z == 4 && blockIdx.y >= DIM / 128) return;   // Wf is only 512 rows

    GEMM_SMEM; GEMM_IDS;
    const float* __restrict__ Wg2 = Wg + (size_t)DIM * DIM;
    const float* __restrict__ Ap = (z == 4) ? Wo : X;
    const float* __restrict__ Bw = (z == 0) ? Wq : (z == 1) ? Wk :
                                   (z == 2) ? Wv : (z == 3) ? Wg : Wg2;
    float* __restrict__ Cc       = (z == 0) ? g_q : (z == 1) ? g_k :
                                   (z == 2) ? g_v : (z == 3) ? g_g1 : g_wf;

    GEMM_ACC_INIT;

    gemm_copy_tile(As[0], Bs[0], tid,
                   &Ap[(size_t)row0 * DIM], DIM, &Bw[col0], DIM);
    int buf = 0;
    for (int k0 = 32; k0 < DIM; k0 += 32) {
        CP_WAIT0(); __syncthreads();
        gemm_copy_tile(As[buf ^ 1], Bs[buf ^ 1], tid,
                       &Ap[(size_t)row0 * DIM + k0], DIM,
                       &Bw[(size_t)k0 * DIM + col0], DIM);
        gemm_compute(As[buf], Bs[buf], warp_m, warp_n, g, tg, acc);
        buf ^= 1;
    }
    CP_WAIT0(); __syncthreads();
    gemm_compute(As[buf], Bs[buf], warp_m, warp_n, g, tg, acc);

#pragma unroll
    for (int mt = 0; mt < 4; mt++) {
        int r0 = row0 + warp_m + mt * 16 + g;
#pragma unroll
        for (int nt = 0; nt < 4; nt++) {
            int c = col0 + warp_n + nt * 8 + tg * 2;
            float v0 = acc[mt][nt][0], v1 = acc[mt][nt][1];
            float v2 = acc[mt][nt][2], v3 = acc[mt][nt][3];
            if (z <= 1) { v0 = fmap(v0); v1 = fmap(v1); v2 = fmap(v2); v3 = fmap(v3); }
            *(float2*)&Cc[(size_t)r0      * DIM + c] = make_float2(v0, v1);
            *(float2*)&Cc[(size_t)(r0 + 8) * DIM + c] = make_float2(v2, v3);
        }
    }

    // bvec = bo @ Wg2 + bg  (z==4, y==0 blocks; 2 threads per column)
    if (z == 4 && blockIdx.y == 0) {
        __shared__ float red[128];
        const int cc   = col0 + (tid & 63);
        const int half = tid >> 6;               // 0 or 1
        float s = 0.f;
        const int kk0 = half * 256;
#pragma unroll 8
        for (int k = kk0; k < kk0 + 256; k++)
            s += bo[k] * Wg2[(size_t)k * DIM + cc];
        red[tid] = s;
        __syncthreads();
        if (half == 0)
            g_bvec[cc] = red[tid] + red[tid + 64] + bg[cc];
    }
}

// ---------------- epilogue GEMMs: z=0 att@Wo -> g_o2, z=1 att@Wf -> g_q -----
__global__ __launch_bounds__(128)
void og_gemm_kernel(const float* __restrict__ Wo)
{
    GEMM_SMEM; GEMM_IDS;
    const int z = blockIdx.z;
    const float* __restrict__ Bw = (z == 0) ? Wo : g_wf;
    float* __restrict__ Cc       = (z == 0) ? g_o2 : g_q;  // g_q dead: reuse as lg

    GEMM_ACC_INIT;

    gemm_copy_tile(As[0], Bs[0], tid,
                   &g_att[(size_t)row0 * DIM], DIM, &Bw[col0], DIM);
    int buf = 0;
    for (int k0 = 32; k0 < DIM; k0 += 32) {
        CP_WAIT0(); __syncthreads();
        gemm_copy_tile(As[buf ^ 1], Bs[buf ^ 1], tid,
                       &g_att[(size_t)row0 * DIM + k0], DIM,
                       &Bw[(size_t)k0 * DIM + col0], DIM);
        gemm_compute(As[buf], Bs[buf], warp_m, warp_n, g, tg, acc);
        buf ^= 1;
    }
    CP_WAIT0(); __syncthreads();
    gemm_compute(As[buf], Bs[buf], warp_m, warp_n, g, tg, acc);

#pragma unroll
    for (int mt = 0; mt < 4; mt++) {
        int r0 = row0 + warp_m + mt * 16 + g;
#pragma unroll
        for (int nt = 0; nt < 4; nt++) {
            int c = col0 + warp_n + nt * 8 + tg * 2;
            *(float2*)&Cc[(size_t)r0      * DIM + c] =
                make_float2(acc[mt][nt][0], acc[mt][nt][1]);
            *(float2*)&Cc[(size_t)(r0 + 8) * DIM + c] =
                make_float2(acc[mt][nt][2], acc[mt][nt][3]);
        }
    }
}

// ---------------- final elementwise: out = x + sig(lg)*(o2+bo - x) ----------
__global__ __launch_bounds__(256)
void final_kernel(const float* __restrict__ X,
                  const float* __restrict__ bo,
                  float* __restrict__ Out)
{
    const int i4 = (blockIdx.x * 256 + threadIdx.x) * 4;   // over MROWS*DIM
    const int c  = i4 & (DIM - 1);

    float4 xv = *(const float4*)&X[i4];
    float4 o2 = *(const float4*)&g_o2[i4];
    float4 lg = *(const float4*)&g_q [i4];
    float4 g1 = *(const float4*)&g_g1[i4];
    float4 b4 = *(const float4*)&bo[c];
    float4 bv = *(const float4*)&g_bvec[c];

    float oo[4] = {o2.x + b4.x, o2.y + b4.y, o2.z + b4.z, o2.w + b4.w};
    float ll[4] = {lg.x + bv.x + g1.x, lg.y + bv.y + g1.y,
                   lg.z + bv.z + g1.z, lg.w + bv.w + g1.w};
    float xx[4] = {xv.x, xv.y, xv.z, xv.w};
    float rr[4];
#pragma unroll
    for (int j = 0; j < 4; j++) {
        float s = 1.f / (1.f + expf(-ll[j]));
        rr[j] = xx[j] + s * (oo[j] - xx[j]);
    }
    *(float4*)&Out[i4] = make_float4(rr[0], rr[1], rr[2], rr[3]);
}

// ---------------- phase A: per-chunk kv sums (2d x 8e register tiles) -------
__global__ __launch_bounds__(256)
void chunk_sums_kernel()
{
    const int bid = blockIdx.x;
    const int c   = bid % NCHK;
    const int bh  = bid / NCHK;
    const int h   = bh % NH;
    const int b   = bh / NH;
    const int row0 = b * SEQ + c * CHK;
    const int col  = h * HD;

    __shared__ float ks[CHK][HD + 4];
    __shared__ float vs[CHK][HD + 4];
    for (int i = threadIdx.x; i < CHK * (HD / 4); i += 256) {
        int t = i / (HD / 4), d4 = (i % (HD / 4)) * 4;
        *(float4*)&ks[t][d4] =
            *(const float4*)&g_k[(size_t)(row0 + t) * DIM + col + d4];
        *(float4*)&vs[t][d4] =
            *(const float4*)&g_v[(size_t)(row0 + t) * DIM + col + d4];
    }
    __syncthreads();

    const int d0 = (threadIdx.x >> 3) * 2;
    const int e0 = (threadIdx.x & 7) * 8;
    float acc[2][8];
#pragma unroll
    for (int i = 0; i < 2; i++)
#pragma unroll
        for (int j = 0; j < 8; j++) acc[i][j] = 0.f;

#pragma unroll
    for (int t = 0; t < CHK; t++) {
        float k0 = ks[t][d0], k1 = ks[t][d0 + 1];
        float4 vA = *(const float4*)&vs[t][e0];
        float4 vB = *(const float4*)&vs[t][e0 + 4];
        acc[0][0] += k0 * vA.x; acc[0][1] += k0 * vA.y;
        acc[0][2] += k0 * vA.z; acc[0][3] += k0 * vA.w;
        acc[0][4] += k0 * vB.x; acc[0][5] += k0 * vB.y;
        acc[0][6] += k0 * vB.z; acc[0][7] += k0 * vB.w;
        acc[1][0] += k1 * vA.x; acc[1][1] += k1 * vA.y;
        acc[1][2] += k1 * vA.z; acc[1][3] += k1 * vA.w;
        acc[1][4] += k1 * vB.x; acc[1][5] += k1 * vB.y;
        acc[1][6] += k1 * vB.z; acc[1][7] += k1 * vB.w;
    }
    const int base = bid * HD * HD;
#pragma unroll
    for (int i = 0; i < 2; i++) {
        *(float4*)&g_kv[base + (d0 + i) * HD + e0] =
            make_float4(acc[i][0], acc[i][1], acc[i][2], acc[i][3]);
        *(float4*)&g_kv[base + (d0 + i) * HD + e0 + 4] =
            make_float4(acc[i][4], acc[i][5], acc[i][6], acc[i][7]);
    }

    if (threadIdx.x < HD) {
        float a = 0.f;
#pragma unroll
        for (int t = 0; t < CHK; t++) a += ks[t][threadIdx.x];
        g_ks[bid * HD + threadIdx.x] = a;
    }
}

// ---------------- phase B: exclusive prefix, front-batched loads ------------
__global__ __launch_bounds__(256)
void prefix_kernel()
{
    const int bh    = blockIdx.x >> 4;            // 0..15
    const int slice = blockIdx.x & 15;            // 0..15
    const int i     = slice * 256 + threadIdx.x;  // 0..4095
    const int stride = HD * HD;
    const int base0  = bh * NCHK * stride + i;

    // all 32 loads independent -> ptxas front-batches them (MLP ~32)
    float v[NCHK];
#pragma unroll
    for (int c = 0; c < NCHK; c++)
        v[c] = g_kv[base0 + c * stride];

    float run = 0.f;
#pragma unroll
    for (int c = 0; c < NCHK; c++) {
        g_kv[base0 + c * stride] = run;
        run += v[c];
    }

    if (slice == 0 && threadIdx.x < HD) {
        const int kbase = bh * NCHK * HD + threadIdx.x;
        float kv[NCHK];
#pragma unroll
        for (int c = 0; c < NCHK; c++)
            kv[c] = g_ks[kbase + c * HD];
        float r = 0.f;
#pragma unroll
        for (int c = 0; c < NCHK; c++) {
            g_ks[kbase + c * HD] = r;
            r += kv[c];
        }
    }
}

// ---------------- phase C: intra-chunk attention (256 thr, 2s x 4e) ---------
__global__ __launch_bounds__(256)
void chunk_out_kernel()
{
    const int bid = blockIdx.x;
    const int c   = bid % NCHK;
    const int bh  = bid / NCHK;
    const int h   = bh % NH;
    const int b   = bh / NH;
    const int row0 = b * SEQ + c * CHK;
    const int col  = h * HD;

    __shared__ float qs [CHK][HD + 4];
    __shared__ float kst_sc[HD * (CHK + 4)];
    __shared__ float vs [CHK][HD + 4];
    __shared__ float kvp[HD][HD + 4];
    __shared__ float kp [HD];
    __shared__ float den[CHK];

    float (*kst)[CHK + 4] = (float(*)[CHK + 4])kst_sc;
    float (*Sc) [CHK + 4] = (float(*)[CHK + 4])kst_sc;

    const int tid = threadIdx.x;
    for (int i = tid; i < CHK * (HD / 4); i += 256) {
        int t = i / (HD / 4), d4 = (i % (HD / 4)) * 4;
        *(float4*)&qs[t][d4] =
            *(const float4*)&g_q[(size_t)(row0 + t) * DIM + col + d4];
        float4 kv4 = *(const float4*)&g_k[(size_t)(row0 + t) * DIM + col + d4];
        kst[d4+0][t] = kv4.x; kst[d4+1][t] = kv4.y;
        kst[d4+2][t] = kv4.z; kst[d4+3][t] = kv4.w;
        *(float4*)&vs[t][d4] =
            *(const float4*)&g_v[(size_t)(row0 + t) * DIM + col + d4];
    }
    const int base = bid * HD * HD;
    for (int i = tid; i < HD * (HD / 4); i += 256) {
        int d = i / (HD / 4), e4 = (i % (HD / 4)) * 4;
        *(float4*)&kvp[d][e4] = *(const float4*)&g_kv[base + d * HD + e4];
    }
    if (tid < HD) kp[tid] = g_ks[bid * HD + tid];
    __syncthreads();

    const int s0 = (tid >> 4) * 2;

    {
        const int t0 = (tid & 15) * 2;
        float a0[2] = {0.f, 0.f};
        float a1[2] = {0.f, 0.f};
#pragma unroll
        for (int d0 = 0; d0 < HD; d0 += 4) {
            float4 qA = *(const float4*)&qs[s0][d0];
            float4 qB = *(const float4*)&qs[s0 + 1][d0];
            float2 kA = *(const float2*)&kst[d0+0][t0];
            float2 kB = *(const float2*)&kst[d0+1][t0];
            float2 kC = *(const float2*)&kst[d0+2][t0];
            float2 kD = *(const float2*)&kst[d0+3][t0];
            a0[0] += qA.x*kA.x + qA.y*kB.x + qA.z*kC.x + qA.w*kD.x;
            a0[1] += qA.x*kA.y + qA.y*kB.y + qA.z*kC.y + qA.w*kD.y;
            a1[0] += qB.x*kA.x + qB.y*kB.x + qB.z*kC.x + qB.w*kD.x;
            a1[1] += qB.x*kA.y + qB.y*kB.y + qB.z*kC.y + qB.w*kD.y;
        }
        __syncthreads();
#pragma unroll
        for (int j = 0; j < 2; j++) {
            Sc[s0    ][t0 + j] = (t0 + j <= s0    ) ? a0[j] : 0.f;
            Sc[s0 + 1][t0 + j] = (t0 + j <= s0 + 1) ? a1[j] : 0.f;
        }
    }
    __syncthreads();

    if (tid < CHK) {
        const int s = tid;
        float a = 0.f;
#pragma unroll
        for (int d0 = 0; d0 < HD; d0 += 4) {
            float4 q4 = *(const float4*)&qs[s][d0];
            float4 k4 = *(const float4*)&kp[d0];
            a += q4.x*k4.x + q4.y*k4.y + q4.z*k4.z + q4.w*k4.w;
        }
#pragma unroll
        for (int tt = 0; tt < CHK; tt += 4) {
            float4 s4 = *(const float4*)&Sc[s][tt];
            a += s4.x + s4.y + s4.z + s4.w;
        }
        den[s] = a + 1e-6f;
    }
    __syncthreads();

    {
        const int e0 = (tid & 15) * 4;
        float b0[4] = {0.f, 0.f, 0.f, 0.f};
        float b1[4] = {0.f, 0.f, 0.f, 0.f};

#pragma unroll
        for (int d0 = 0; d0 < HD; d0 += 4) {
            float4 qA = *(const float4*)&qs[s0][d0];
            float4 qB = *(const float4*)&qs[s0 + 1][d0];
            float qa[4] = {qA.x, qA.y, qA.z, qA.w};
            float qb[4] = {qB.x, qB.y, qB.z, qB.w};
#pragma unroll
            for (int dd = 0; dd < 4; dd++) {
                float4 vA = *(const float4*)&kvp[d0 + dd][e0];
                b0[0] += qa[dd] * vA.x; b0[1] += qa[dd] * vA.y;
                b0[2] += qa[dd] * vA.z; b0[3] += qa[dd] * vA.w;
                b1[0] += qb[dd] * vA.x; b1[1] += qb[dd] * vA.y;
                b1[2] += qb[dd] * vA.z; b1[3] += qb[dd] * vA.w;
            }
        }
#pragma unroll
        for (int tt0 = 0; tt0 < CHK; tt0 += 4) {
            float4 sA = *(const float4*)&Sc[s0][tt0];
            float4 sB = *(const float4*)&Sc[s0 + 1][tt0];
            float sa[4] = {sA.x, sA.y, sA.z, sA.w};
            float sb[4] = {sB.x, sB.y, sB.z, sB.w};
#pragma unroll
            for (int tt = 0; tt < 4; tt++) {
                float4 vA = *(const float4*)&vs[tt0 + tt][e0];
                b0[0] += sa[tt] * vA.x; b0[1] += sa[tt] * vA.y;
                b0[2] += sa[tt] * vA.z; b0[3] += sa[tt] * vA.w;
                b1[0] += sb[tt] * vA.x; b1[1] += sb[tt] * vA.y;
                b1[2] += sb[tt] * vA.z; b1[3] += sb[tt] * vA.w;
            }
        }
        const float inv0 = 1.f / den[s0];
        const float inv1 = 1.f / den[s0 + 1];
        float* d0p = &g_att[(size_t)(row0 + s0)     * DIM + col + e0];
        float* d1p = &g_att[(size_t)(row0 + s0 + 1) * DIM + col + e0];
        *(float4*)d0p = make_float4(b0[0]*inv0, b0[1]*inv0, b0[2]*inv0, b0[3]*inv0);
        *(float4*)d1p = make_float4(b1[0]*inv1, b1[1]*inv1, b1[2]*inv1, b1[3]*inv1);
    }
}

// ---------------- launcher --------------------------------------------------
extern "C" void kernel_launch(void* const* d_in, const int* in_sizes, int n_in,
                              void* d_out, int out_size)
{
    const float* x  = (const float*)d_in[0];
    const float* Wq = (const float*)d_in[1];
    const float* Wk = (const float*)d_in[2];
    const float* Wv = (const float*)d_in[3];
    const float* Wo = (const float*)d_in[4];
    const float* bo = (const float*)d_in[5];
    const float* Wg = (const float*)d_in[6];
    const float* bg = (const float*)d_in[7];
    float* out = (float*)d_out;

    cudaFuncSetAttribute(qkv_gemm_kernel,
        cudaFuncAttributeMaxDynamicSharedMemorySize, GEMM_SMEM_BYTES);
    cudaFuncSetAttribute(og_gemm_kernel,
        cudaFuncAttributeMaxDynamicSharedMemorySize, GEMM_SMEM_BYTES);

    dim3 grid5(DIM / 64, MROWS / 128, 5);   // QKV + G1 + Wf in one wave
    dim3 grid2(DIM / 64, MROWS / 128, 2);   // o2 + lg in one wave

    qkv_gemm_kernel<<<grid5, 128, GEMM_SMEM_BYTES>>>(x, Wq, Wk, Wv, Wo, Wg, bo, bg);
    chunk_sums_kernel<<<NBLK, 256>>>();
    prefix_kernel<<<NBH * 16, 256>>>();
    chunk_out_kernel<<<NBLK, 256>>>();
    og_gemm_kernel<<<grid2, 128, GEMM_SMEM_BYTES>>>(Wo);
    final_kernel<<<MROWS * DIM / 1024, 256>>>(x, bo, out);
}

// round 17
// speedup vs baseline: 1.3182x; 1.1360x over previous
#include <cuda_runtime.h>
#include <math.h>
#include <stdint.h>

#define BATCH 2
#define SEQ   1024
#define DIM   512
#define NH    8
#define HD    64
#define MROWS (BATCH*SEQ)      // 2048
#define CHK   32
#define NCHK  (SEQ/CHK)        // 32
#define NBH   (BATCH*NH)       // 16
#define NBLK  (NBH*NCHK)       // 512

// ---------------- scratch ---------------------------------------------------
__device__ float g_q  [MROWS*DIM];   // q; reused as lg_raw after chunk_out
__device__ float g_k  [MROWS*DIM];
__device__ float g_v  [MROWS*DIM];
__device__ float g_att[MROWS*DIM];
__device__ float g_o2 [MROWS*DIM];   // raw att@Wo
__device__ float g_g1 [MROWS*DIM];   // x @ Wg[:512]
__device__ float g_wf [DIM*DIM];     // Wo @ Wg2
__device__ float g_bvec[DIM];        // bo @ Wg2 + bg
__device__ float g_kv [NBLK*HD*HD];
__device__ float g_ks [NBLK*HD];

__device__ __forceinline__ float fmap(float t) {
    return t > 0.f ? t + 1.f : expf(t);
}

__device__ __forceinline__ void mma_tf32(float c[4],
    uint32_t a0, uint32_t a1, uint32_t a2, uint32_t a3,
    uint32_t b0, uint32_t b1)
{
    asm volatile(
        "mma.sync.aligned.m16n8k8.row.col.f32.tf32.tf32.f32 "
        "{%0,%1,%2,%3},{%4,%5,%6,%7},{%8,%9},{%0,%1,%2,%3};"
        : "+f"(c[0]), "+f"(c[1]), "+f"(c[2]), "+f"(c[3])
        : "r"(a0), "r"(a1), "r"(a2), "r"(a3), "r"(b0), "r"(b1));
}

__device__ __forceinline__ void cp16(void* smem_dst, const void* gsrc) {
    uint32_t d = (uint32_t)__cvta_generic_to_shared(smem_dst);
    asm volatile("cp.async.cg.shared.global [%0], [%1], 16;" :: "r"(d), "l"(gsrc));
}
#define CP_COMMIT() asm volatile("cp.async.commit_group;")
#define CP_WAIT0()  asm volatile("cp.async.wait_group 0;")

// ======================= tf32 GEMM framework ================================
#define AS_STRIDE 36
#define BS_STRIDE 72
#define AS_WORDS  (128 * AS_STRIDE)
#define BS_WORDS  (32 * BS_STRIDE)
#define GEMM_SMEM_BYTES ((2 * AS_WORDS + 2 * BS_WORDS) * 4)   // 55296

typedef uint32_t AsBuf[128][AS_STRIDE];
typedef uint32_t BsBuf[32][BS_STRIDE];

#define GEMM_SMEM \
    extern __shared__ uint32_t dynsmem[]; \
    AsBuf* As = (AsBuf*)dynsmem; \
    BsBuf* Bs = (BsBuf*)(dynsmem + 2 * AS_WORDS);

#define GEMM_IDS \
    const int tid  = threadIdx.x; \
    const int lane = tid & 31, wid = tid >> 5; \
    const int g    = lane >> 2, tg = lane & 3; \
    const int warp_m = (wid >> 1) * 64, warp_n = (wid & 1) * 32; \
    const int row0 = blockIdx.y * 128, col0 = blockIdx.x * 64;

__device__ __forceinline__ void gemm_copy_tile(
    uint32_t (*Asb)[AS_STRIDE], uint32_t (*Bsb)[BS_STRIDE], int tid,
    const float* Ag, size_t lda, const float* Bg, size_t ldb)
{
    const int ar = tid >> 3;
    const int ac = (tid & 7) * 4;
#pragma unroll
    for (int p = 0; p < 8; p++)
        cp16(&Asb[ar + p * 16][ac], Ag + (size_t)(ar + p * 16) * lda + ac);
#pragma unroll
    for (int p = 0; p < 4; p++) {
        int idx = tid + p * 128;
        int br  = idx >> 4;
        int bc  = (idx & 15) * 4;
        cp16(&Bsb[br][bc], Bg + (size_t)br * ldb + bc);
    }
    CP_COMMIT();
}

__device__ __forceinline__ void gemm_compute(
    uint32_t (*Asb)[AS_STRIDE], uint32_t (*Bsb)[BS_STRIDE],
    int warp_m, int warp_n, int g, int tg, float acc[4][4][4])
{
#pragma unroll
    for (int ks = 0; ks < 4; ks++) {
        uint32_t af[4][4];
#pragma unroll
        for (int mt = 0; mt < 4; mt++) {
            int base = warp_m + mt * 16;
            af[mt][0] = Asb[base + g    ][ks * 8 + tg];
            af[mt][1] = Asb[base + g + 8][ks * 8 + tg];
            af[mt][2] = Asb[base + g    ][ks * 8 + tg + 4];
            af[mt][3] = Asb[base + g + 8][ks * 8 + tg + 4];
        }
        uint32_t bf[4][2];
#pragma unroll
        for (int nt = 0; nt < 4; nt++) {
            int col = warp_n + nt * 8 + g;
            bf[nt][0] = Bsb[ks * 8 + tg    ][col];
            bf[nt][1] = Bsb[ks * 8 + tg + 4][col];
        }
#pragma unroll
        for (int mt = 0; mt < 4; mt++)
#pragma unroll
            for (int nt = 0; nt < 4; nt++)
                mma_tf32(acc[mt][nt], af[mt][0], af[mt][1], af[mt][2], af[mt][3],
                         bf[nt][0], bf[nt][1]);
    }
}

#define GEMM_ACC_INIT \
    float acc[4][4][4]; \
    _Pragma("unroll") \
    for (int mt = 0; mt < 4; mt++) \
        _Pragma("unroll") \
        for (int nt = 0; nt < 4; nt++) \
            _Pragma("unroll") \
            for (int i = 0; i < 4; i++) acc[mt][nt][i] = 0.f;

// ------- fused QKV+G1+Wf GEMM (z: 0=q,1=k,2=v,3=g1,4=Wf[y<4]) ---------------
__global__ __launch_bounds__(128)
void qkv_gemm_kernel(const float* __restrict__ X,
                     const float* __restrict__ Wq,
                     const float* __restrict__ Wk,
                     const float* __restrict__ Wv,
                     const float* __restrict__ Wo,
                     const float* __restrict__ Wg,
                     const float* __restrict__ bo,
                     const float* __restrict__ bg)
{
    const int z = blockIdx.z;
    if (z == 4 && blockIdx.y >= DIM / 128) return;   // Wf is only 512 rows

    GEMM_SMEM; GEMM_IDS;
    const float* __restrict__ Wg2 = Wg + (size_t)DIM * DIM;
    const float* __restrict__ Ap = (z == 4) ? Wo : X;
    const float* __restrict__ Bw = (z == 0) ? Wq : (z == 1) ? Wk :
                                   (z == 2) ? Wv : (z == 3) ? Wg : Wg2;
    float* __restrict__ Cc       = (z == 0) ? g_q : (z == 1) ? g_k :
                                   (z == 2) ? g_v : (z == 3) ? g_g1 : g_wf;

    GEMM_ACC_INIT;

    gemm_copy_tile(As[0], Bs[0], tid,
                   &Ap[(size_t)row0 * DIM], DIM, &Bw[col0], DIM);
    int buf = 0;
    for (int k0 = 32; k0 < DIM; k0 += 32) {
        CP_WAIT0(); __syncthreads();
        gemm_copy_tile(As[buf ^ 1], Bs[buf ^ 1], tid,
                       &Ap[(size_t)row0 * DIM + k0], DIM,
                       &Bw[(size_t)k0 * DIM + col0], DIM);
        gemm_compute(As[buf], Bs[buf], warp_m, warp_n, g, tg, acc);
        buf ^= 1;
    }
    CP_WAIT0(); __syncthreads();
    gemm_compute(As[buf], Bs[buf], warp_m, warp_n, g, tg, acc);

#pragma unroll
    for (int mt = 0; mt < 4; mt++) {
        int r0 = row0 + warp_m + mt * 16 + g;
#pragma unroll
        for (int nt = 0; nt < 4; nt++) {
            int c = col0 + warp_n + nt * 8 + tg * 2;
            float v0 = acc[mt][nt][0], v1 = acc[mt][nt][1];
            float v2 = acc[mt][nt][2], v3 = acc[mt][nt][3];
            if (z <= 1) { v0 = fmap(v0); v1 = fmap(v1); v2 = fmap(v2); v3 = fmap(v3); }
            *(float2*)&Cc[(size_t)r0      * DIM + c] = make_float2(v0, v1);
            *(float2*)&Cc[(size_t)(r0 + 8) * DIM + c] = make_float2(v2, v3);
        }
    }

    if (z == 4 && blockIdx.y == 0) {
        __shared__ float red[128];
        const int cc   = col0 + (tid & 63);
        const int half = tid >> 6;
        float s = 0.f;
        const int kk0 = half * 256;
#pragma unroll 8
        for (int k = kk0; k < kk0 + 256; k++)
            s += bo[k] * Wg2[(size_t)k * DIM + cc];
        red[tid] = s;
        __syncthreads();
        if (half == 0)
            g_bvec[cc] = red[tid] + red[tid + 64] + bg[cc];
    }
}

// ---------------- epilogue GEMMs: z=0 att@Wo -> g_o2, z=1 att@Wf -> g_q -----
__global__ __launch_bounds__(128)
void og_gemm_kernel(const float* __restrict__ Wo)
{
    GEMM_SMEM; GEMM_IDS;
    const int z = blockIdx.z;
    const float* __restrict__ Bw = (z == 0) ? Wo : g_wf;
    float* __restrict__ Cc       = (z == 0) ? g_o2 : g_q;

    GEMM_ACC_INIT;

    gemm_copy_tile(As[0], Bs[0], tid,
                   &g_att[(size_t)row0 * DIM], DIM, &Bw[col0], DIM);
    int buf = 0;
    for (int k0 = 32; k0 < DIM; k0 += 32) {
        CP_WAIT0(); __syncthreads();
        gemm_copy_tile(As[buf ^ 1], Bs[buf ^ 1], tid,
                       &g_att[(size_t)row0 * DIM + k0], DIM,
                       &Bw[(size_t)k0 * DIM + col0], DIM);
        gemm_compute(As[buf], Bs[buf], warp_m, warp_n, g, tg, acc);
        buf ^= 1;
    }
    CP_WAIT0(); __syncthreads();
    gemm_compute(As[buf], Bs[buf], warp_m, warp_n, g, tg, acc);

#pragma unroll
    for (int mt = 0; mt < 4; mt++) {
        int r0 = row0 + warp_m + mt * 16 + g;
#pragma unroll
        for (int nt = 0; nt < 4; nt++) {
            int c = col0 + warp_n + nt * 8 + tg * 2;
            *(float2*)&Cc[(size_t)r0      * DIM + c] =
                make_float2(acc[mt][nt][0], acc[mt][nt][1]);
            *(float2*)&Cc[(size_t)(r0 + 8) * DIM + c] =
                make_float2(acc[mt][nt][2], acc[mt][nt][3]);
        }
    }
}

// ---------------- final elementwise: out = x + sig(lg)*(o2+bo - x) ----------
__global__ __launch_bounds__(256)
void final_kernel(const float* __restrict__ X,
                  const float* __restrict__ bo,
                  float* __restrict__ Out)
{
    const int i4 = (blockIdx.x * 256 + threadIdx.x) * 4;
    const int c  = i4 & (DIM - 1);

    float4 xv = *(const float4*)&X[i4];
    float4 o2 = *(const float4*)&g_o2[i4];
    float4 lg = *(const float4*)&g_q [i4];
    float4 g1 = *(const float4*)&g_g1[i4];
    float4 b4 = *(const float4*)&bo[c];
    float4 bv = *(const float4*)&g_bvec[c];

    float oo[4] = {o2.x + b4.x, o2.y + b4.y, o2.z + b4.z, o2.w + b4.w};
    float ll[4] = {lg.x + bv.x + g1.x, lg.y + bv.y + g1.y,
                   lg.z + bv.z + g1.z, lg.w + bv.w + g1.w};
    float xx[4] = {xv.x, xv.y, xv.z, xv.w};
    float rr[4];
#pragma unroll
    for (int j = 0; j < 4; j++) {
        float s = 1.f / (1.f + expf(-ll[j]));
        rr[j] = xx[j] + s * (oo[j] - xx[j]);
    }
    *(float4*)&Out[i4] = make_float4(rr[0], rr[1], rr[2], rr[3]);
}

// ---------------- phase A: per-chunk kv sums via tensor cores ---------------
// C[d][e] = sum_t K[t][d]*V[t][e] : A = kst[d][t] (64x32), B = vs[t][e]
__global__ __launch_bounds__(256)
void chunk_sums_kernel()
{
    const int bid = blockIdx.x;
    const int c   = bid % NCHK;
    const int bh  = bid / NCHK;
    const int h   = bh % NH;
    const int b   = bh / NH;
    const int row0 = b * SEQ + c * CHK;
    const int col  = h * HD;

    __shared__ float kst[HD][CHK + 4];     // k transposed: kst[d][t]
    __shared__ float vs [CHK][HD + 4];     // v natural: vs[t][e]

    const int tid = threadIdx.x;
    for (int i = tid; i < CHK * (HD / 4); i += 256) {
        int t = i / (HD / 4), d4 = (i % (HD / 4)) * 4;
        float4 kv4 = *(const float4*)&g_k[(size_t)(row0 + t) * DIM + col + d4];
        kst[d4+0][t] = kv4.x; kst[d4+1][t] = kv4.y;
        kst[d4+2][t] = kv4.z; kst[d4+3][t] = kv4.w;
        *(float4*)&vs[t][d4] =
            *(const float4*)&g_v[(size_t)(row0 + t) * DIM + col + d4];
    }
    __syncthreads();

    const int lane = tid & 31, wid = tid >> 5;
    const int g  = lane >> 2, tg = lane & 3;
    const int m0 = (wid >> 1) * 16;        // d tile
    const int nb = (wid & 1) * 32;         // e tile group (4 n-tiles)

    float cc[4][4];
#pragma unroll
    for (int j = 0; j < 4; j++)
#pragma unroll
        for (int i = 0; i < 4; i++) cc[j][i] = 0.f;

#pragma unroll
    for (int k0 = 0; k0 < CHK; k0 += 8) {
        uint32_t a0 = __float_as_uint(kst[m0 + g    ][k0 + tg]);
        uint32_t a1 = __float_as_uint(kst[m0 + g + 8][k0 + tg]);
        uint32_t a2 = __float_as_uint(kst[m0 + g    ][k0 + tg + 4]);
        uint32_t a3 = __float_as_uint(kst[m0 + g + 8][k0 + tg + 4]);
#pragma unroll
        for (int j = 0; j < 4; j++) {
            int n0 = nb + j * 8;
            uint32_t b0 = __float_as_uint(vs[k0 + tg    ][n0 + g]);
            uint32_t b1 = __float_as_uint(vs[k0 + tg + 4][n0 + g]);
            mma_tf32(cc[j], a0, a1, a2, a3, b0, b1);
        }
    }
    const int base = bid * HD * HD;
#pragma unroll
    for (int j = 0; j < 4; j++) {
        int n0 = nb + j * 8 + tg * 2;
        *(float2*)&g_kv[base + (m0 + g    ) * HD + n0] = make_float2(cc[j][0], cc[j][1]);
        *(float2*)&g_kv[base + (m0 + g + 8) * HD + n0] = make_float2(cc[j][2], cc[j][3]);
    }

    if (tid < HD) {
        float a = 0.f;
#pragma unroll
        for (int t = 0; t < CHK; t++) a += kst[tid][t];
        g_ks[bid * HD + tid] = a;
    }
}

// ---------------- phase B: exclusive prefix, front-batched loads ------------
__global__ __launch_bounds__(256)
void prefix_kernel()
{
    const int bh    = blockIdx.x >> 4;
    const int slice = blockIdx.x & 15;
    const int i     = slice * 256 + threadIdx.x;
    const int stride = HD * HD;
    const int base0  = bh * NCHK * stride + i;

    float v[NCHK];
#pragma unroll
    for (int c = 0; c < NCHK; c++)
        v[c] = g_kv[base0 + c * stride];

    float run = 0.f;
#pragma unroll
    for (int c = 0; c < NCHK; c++) {
        g_kv[base0 + c * stride] = run;
        run += v[c];
    }

    if (slice == 0 && threadIdx.x < HD) {
        const int kbase = bh * NCHK * HD + threadIdx.x;
        float kv[NCHK];
#pragma unroll
        for (int c = 0; c < NCHK; c++)
            kv[c] = g_ks[kbase + c * HD];
        float r = 0.f;
#pragma unroll
        for (int c = 0; c < NCHK; c++) {
            g_ks[kbase + c * HD] = r;
            r += kv[c];
        }
    }
}

// ---------------- phase C: intra-chunk attention via tensor cores -----------
// S = Q @ K^T (A=qs, B=kst); OUT = Q @ KVP + Sc @ V (B=kvp, vs natural)
__global__ __launch_bounds__(256)
void chunk_out_kernel()
{
    const int bid = blockIdx.x;
    const int c   = bid % NCHK;
    const int bh  = bid / NCHK;
    const int h   = bh % NH;
    const int b   = bh / NH;
    const int row0 = b * SEQ + c * CHK;
    const int col  = h * HD;

    __shared__ float qs [CHK][HD + 4];
    __shared__ float kst[HD][CHK + 4];
    __shared__ float vs [CHK][HD + 4];
    __shared__ float kvp[HD][HD + 4];
    __shared__ float Sc [CHK][CHK + 4];
    __shared__ float kp [HD];
    __shared__ float den[CHK];

    const int tid = threadIdx.x;
    for (int i = tid; i < CHK * (HD / 4); i += 256) {
        int t = i / (HD / 4), d4 = (i % (HD / 4)) * 4;
        *(float4*)&qs[t][d4] =
            *(const float4*)&g_q[(size_t)(row0 + t) * DIM + col + d4];
        float4 kv4 = *(const float4*)&g_k[(size_t)(row0 + t) * DIM + col + d4];
        kst[d4+0][t] = kv4.x; kst[d4+1][t] = kv4.y;
        kst[d4+2][t] = kv4.z; kst[d4+3][t] = kv4.w;
        *(float4*)&vs[t][d4] =
            *(const float4*)&g_v[(size_t)(row0 + t) * DIM + col + d4];
    }
    const int base = bid * HD * HD;
    for (int i = tid; i < HD * (HD / 4); i += 256) {
        int d = i / (HD / 4), e4 = (i % (HD / 4)) * 4;
        *(float4*)&kvp[d][e4] = *(const float4*)&g_kv[base + d * HD + e4];
    }
    if (tid < HD) kp[tid] = g_ks[bid * HD + tid];
    __syncthreads();

    const int lane = tid & 31, wid = tid >> 5;
    const int g  = lane >> 2, tg = lane & 3;

    // ---- scores: warp tile (mS, nS); M=32 x N=32, K=64 ----
    {
        const int mS = (wid >> 2) * 16;
        const int nS = (wid & 3) * 8;
        float cS[4] = {0.f, 0.f, 0.f, 0.f};
#pragma unroll
        for (int k0 = 0; k0 < HD; k0 += 8) {
            uint32_t a0 = __float_as_uint(qs[mS + g    ][k0 + tg]);
            uint32_t a1 = __float_as_uint(qs[mS + g + 8][k0 + tg]);
            uint32_t a2 = __float_as_uint(qs[mS + g    ][k0 + tg + 4]);
            uint32_t a3 = __float_as_uint(qs[mS + g + 8][k0 + tg + 4]);
            uint32_t b0 = __float_as_uint(kst[k0 + tg    ][nS + g]);
            uint32_t b1 = __float_as_uint(kst[k0 + tg + 4][nS + g]);
            mma_tf32(cS, a0, a1, a2, a3, b0, b1);
        }
        const int t0  = nS + tg * 2;
        const int s_a = mS + g, s_b = mS + g + 8;
        Sc[s_a][t0]     = (t0     <= s_a) ? cS[0] : 0.f;
        Sc[s_a][t0 + 1] = (t0 + 1 <= s_a) ? cS[1] : 0.f;
        Sc[s_b][t0]     = (t0     <= s_b) ? cS[2] : 0.f;
        Sc[s_b][t0 + 1] = (t0 + 1 <= s_b) ? cS[3] : 0.f;
    }
    __syncthreads();

    if (tid < CHK) {
        const int s = tid;
        float a = 0.f;
#pragma unroll
        for (int d0 = 0; d0 < HD; d0 += 4) {
            float4 q4 = *(const float4*)&qs[s][d0];
            float4 k4 = *(const float4*)&kp[d0];
            a += q4.x*k4.x + q4.y*k4.y + q4.z*k4.z + q4.w*k4.w;
        }
#pragma unroll
        for (int tt = 0; tt < CHK; tt += 4) {
            float4 s4 = *(const float4*)&Sc[s][tt];
            a += s4.x + s4.y + s4.z + s4.w;
        }
        den[s] = a + 1e-6f;
    }
    __syncthreads();

    // ---- output: warp handles (mO, 2 n-tiles); C = Q@KVP + Sc@V ----
    {
        const int mO = (wid >> 2) * 16;
        const int n0 = ((wid & 3) * 2) * 8;
        const int n1 = n0 + 8;
        float c0[4] = {0.f, 0.f, 0.f, 0.f};
        float c1[4] = {0.f, 0.f, 0.f, 0.f};

#pragma unroll
        for (int k0 = 0; k0 < HD; k0 += 8) {      // Q @ KVP, K=64
            uint32_t a0 = __float_as_uint(qs[mO + g    ][k0 + tg]);
            uint32_t a1 = __float_as_uint(qs[mO + g + 8][k0 + tg]);
            uint32_t a2 = __float_as_uint(qs[mO + g    ][k0 + tg + 4]);
            uint32_t a3 = __float_as_uint(qs[mO + g + 8][k0 + tg + 4]);
            uint32_t b0 = __float_as_uint(kvp[k0 + tg    ][n0 + g]);
            uint32_t b1 = __float_as_uint(kvp[k0 + tg + 4][n0 + g]);
            mma_tf32(c0, a0, a1, a2, a3, b0, b1);
            uint32_t b2 = __float_as_uint(kvp[k0 + tg    ][n1 + g]);
            uint32_t b3 = __float_as_uint(kvp[k0 + tg + 4][n1 + g]);
            mma_tf32(c1, a0, a1, a2, a3, b2, b3);
        }
#pragma unroll
        for (int k0 = 0; k0 < CHK; k0 += 8) {     // Sc @ V, K=32
            uint32_t a0 = __float_as_uint(Sc[mO + g    ][k0 + tg]);
            uint32_t a1 = __float_as_uint(Sc[mO + g + 8][k0 + tg]);
            uint32_t a2 = __float_as_uint(Sc[mO + g    ][k0 + tg + 4]);
            uint32_t a3 = __float_as_uint(Sc[mO + g + 8][k0 + tg + 4]);
            uint32_t b0 = __float_as_uint(vs[k0 + tg    ][n0 + g]);
            uint32_t b1 = __float_as_uint(vs[k0 + tg + 4][n0 + g]);
            mma_tf32(c0, a0, a1, a2, a3, b0, b1);
            uint32_t b2 = __float_as_uint(vs[k0 + tg    ][n1 + g]);
            uint32_t b3 = __float_as_uint(vs[k0 + tg + 4][n1 + g]);
            mma_tf32(c1, a0, a1, a2, a3, b2, b3);
        }

        const float inv_a = 1.f / den[mO + g];
        const float inv_b = 1.f / den[mO + g + 8];
        float* ra = &g_att[(size_t)(row0 + mO + g    ) * DIM + col];
        float* rb = &g_att[(size_t)(row0 + mO + g + 8) * DIM + col];
        *(float2*)&ra[n0 + tg * 2] = make_float2(c0[0] * inv_a, c0[1] * inv_a);
        *(float2*)&rb[n0 + tg * 2] = make_float2(c0[2] * inv_b, c0[3] * inv_b);
        *(float2*)&ra[n1 + tg * 2] = make_float2(c1[0] * inv_a, c1[1] * inv_a);
        *(float2*)&rb[n1 + tg * 2] = make_float2(c1[2] * inv_b, c1[3] * inv_b);
    }
}

// ---------------- launcher --------------------------------------------------
extern "C" void kernel_launch(void* const* d_in, const int* in_sizes, int n_in,
                              void* d_out, int out_size)
{
    const float* x  = (const float*)d_in[0];
    const float* Wq = (const float*)d_in[1];
    const float* Wk = (const float*)d_in[2];
    const float* Wv = (const float*)d_in[3];
    const float* Wo = (const float*)d_in[4];
    const float* bo = (const float*)d_in[5];
    const float* Wg = (const float*)d_in[6];
    const float* bg = (const float*)d_in[7];
    float* out = (float*)d_out;

    cudaFuncSetAttribute(qkv_gemm_kernel,
        cudaFuncAttributeMaxDynamicSharedMemorySize, GEMM_SMEM_BYTES);
    cudaFuncSetAttribute(og_gemm_kernel,
        cudaFuncAttributeMaxDynamicSharedMemorySize, GEMM_SMEM_BYTES);

    dim3 grid5(DIM / 64, MROWS / 128, 5);   // QKV + G1 + Wf in one wave
    dim3 grid2(DIM / 64, MROWS / 128, 2);   // o2 + lg in one wave

    qkv_gemm_kernel<<<grid5, 128, GEMM_SMEM_BYTES>>>(x, Wq, Wk, Wv, Wo, Wg, bo, bg);
    chunk_sums_kernel<<<NBLK, 256>>>();
    prefix_kernel<<<NBH * 16, 256>>>();
    chunk_out_kernel<<<NBLK, 256>>>();
    og_gemm_kernel<<<grid2, 128, GEMM_SMEM_BYTES>>>(Wo);
    final_kernel<<<MROWS * DIM / 1024, 256>>>(x, bo, out);
}